// round 3
// baseline (speedup 1.0000x reference)
#include <cuda_runtime.h>
#include <math.h>

#define HIDDEN 2048
#define NH 16
#define HD 128
#define BATCH 2
#define SEQ 2048
#define ROWS (BATCH*SEQ)   /* 4096 */

// Scratch (allocation-free: __device__ globals)
__device__ float g_Q[ROWS * HIDDEN];
__device__ float g_K[ROWS * HIDDEN];
__device__ float g_V[ROWS * HIDDEN];
__device__ float g_ctx[ROWS * HIDDEN];
__device__ float g_S[134217728];   /* 32 * 2048 * 2048 scores/probs */

#define ASTRIDE 260   /* padded row stride (floats) for duplicated A tile */

__device__ __forceinline__ void fma2(unsigned long long& acc,
                                     unsigned long long a,
                                     unsigned long long b)
{
    asm("fma.rn.f32x2 %0, %1, %2, %0;" : "+l"(acc) : "l"(a), "l"(b));
}

__device__ __forceinline__ unsigned long long mul2(unsigned long long a,
                                                   unsigned long long b)
{
    unsigned long long r;
    asm("mul.rn.f32x2 %0, %1, %2;" : "=l"(r) : "l"(a), "l"(b));
    return r;
}

// ---------------------------------------------------------------------------
// C[M,N] = alpha * A[M,K] @ B[N,K]^T   (both K-contiguous / row-major)
// 128x128 tile, BK=16, 256 threads, 8x8 per-thread microtile via f32x2 pairs.
// ---------------------------------------------------------------------------
__global__ __launch_bounds__(256) void gemm_nt(
    const float* __restrict__ A, int lda, long long saB, long long saH,
    const float* __restrict__ B, int ldb, long long sbB, long long sbH,
    float* __restrict__ C, int ldc, long long scB, long long scH,
    int K, float alpha)
{
    __shared__ float As2[16][ASTRIDE];  // duplicated pairs: [k][2m],[k][2m+1]
    __shared__ float Bs[16][128];

    const int z  = blockIdx.z;
    const long long zb = z >> 4, zh = z & 15;
    A += zb * saB + zh * saH + (long long)blockIdx.y * 128 * lda;
    B += zb * sbB + zh * sbH + (long long)blockIdx.x * 128 * ldb;
    C += zb * scB + zh * scH + (long long)blockIdx.y * 128 * ldc
                             + (long long)blockIdx.x * 128;

    const int tid = threadIdx.x;
    const int tx = tid & 15, ty = tid >> 4;

    unsigned long long acc2[8][4];
    #pragma unroll
    for (int i = 0; i < 8; i++)
        #pragma unroll
        for (int j = 0; j < 4; j++) acc2[i][j] = 0ull;  // (0.0f,0.0f)

    for (int kt = 0; kt < K; kt += 16) {
        #pragma unroll
        for (int l = 0; l < 2; l++) {
            int L = tid + l * 256;
            int row = L >> 2;
            int cv  = (L & 3) * 4;
            float4 a = *(const float4*)(A + (long long)row * lda + kt + cv);
            *(float2*)&As2[cv + 0][2 * row] = make_float2(a.x, a.x);
            *(float2*)&As2[cv + 1][2 * row] = make_float2(a.y, a.y);
            *(float2*)&As2[cv + 2][2 * row] = make_float2(a.z, a.z);
            *(float2*)&As2[cv + 3][2 * row] = make_float2(a.w, a.w);
            float4 b = *(const float4*)(B + (long long)row * ldb + kt + cv);
            Bs[cv + 0][row] = b.x; Bs[cv + 1][row] = b.y;
            Bs[cv + 2][row] = b.z; Bs[cv + 3][row] = b.w;
        }
        __syncthreads();
        #pragma unroll
        for (int k = 0; k < 16; k++) {
            unsigned long long aa[8], bb[4];
            ulonglong2 t0 = *(const ulonglong2*)&As2[k][ty * 16];
            ulonglong2 t1 = *(const ulonglong2*)&As2[k][ty * 16 + 4];
            ulonglong2 t2 = *(const ulonglong2*)&As2[k][ty * 16 + 8];
            ulonglong2 t3 = *(const ulonglong2*)&As2[k][ty * 16 + 12];
            aa[0] = t0.x; aa[1] = t0.y; aa[2] = t1.x; aa[3] = t1.y;
            aa[4] = t2.x; aa[5] = t2.y; aa[6] = t3.x; aa[7] = t3.y;
            ulonglong2 u0 = *(const ulonglong2*)&Bs[k][tx * 8];
            ulonglong2 u1 = *(const ulonglong2*)&Bs[k][tx * 8 + 4];
            bb[0] = u0.x; bb[1] = u0.y; bb[2] = u1.x; bb[3] = u1.y;
            #pragma unroll
            for (int i = 0; i < 8; i++)
                #pragma unroll
                for (int j = 0; j < 4; j++)
                    fma2(acc2[i][j], aa[i], bb[j]);
        }
        __syncthreads();
    }

    unsigned long long alpha2;
    asm("mov.b64 %0, {%1, %1};" : "=l"(alpha2) : "f"(alpha));
    #pragma unroll
    for (int i = 0; i < 8; i++) {
        ulonglong2 o0, o1;
        o0.x = mul2(acc2[i][0], alpha2);
        o0.y = mul2(acc2[i][1], alpha2);
        o1.x = mul2(acc2[i][2], alpha2);
        o1.y = mul2(acc2[i][3], alpha2);
        float* cr = C + (long long)(ty * 8 + i) * ldc + tx * 8;
        *(ulonglong2*)(cr)     = o0;
        *(ulonglong2*)(cr + 4) = o1;
    }
}

// ---------------------------------------------------------------------------
// C[M,N] = A[M,K] @ B[K,N]   (A K-contiguous, B N-contiguous)  -- for P@V
// ---------------------------------------------------------------------------
__global__ __launch_bounds__(256) void gemm_nn(
    const float* __restrict__ A, int lda, long long saB, long long saH,
    const float* __restrict__ B, int ldb, long long sbB, long long sbH,
    float* __restrict__ C, int ldc, long long scB, long long scH,
    int K)
{
    __shared__ float As2[16][ASTRIDE];
    __shared__ float Bs[16][128];

    const int z  = blockIdx.z;
    const long long zb = z >> 4, zh = z & 15;
    A += zb * saB + zh * saH + (long long)blockIdx.y * 128 * lda;
    B += zb * sbB + zh * sbH + (long long)blockIdx.x * 128;
    C += zb * scB + zh * scH + (long long)blockIdx.y * 128 * ldc
                             + (long long)blockIdx.x * 128;

    const int tid = threadIdx.x;
    const int tx = tid & 15, ty = tid >> 4;

    unsigned long long acc2[8][4];
    #pragma unroll
    for (int i = 0; i < 8; i++)
        #pragma unroll
        for (int j = 0; j < 4; j++) acc2[i][j] = 0ull;

    for (int kt = 0; kt < K; kt += 16) {
        #pragma unroll
        for (int l = 0; l < 2; l++) {
            int L = tid + l * 256;
            // A tile (duplicated transpose into As2[k][2m..2m+1])
            int row = L >> 2;
            int cv  = (L & 3) * 4;
            float4 a = *(const float4*)(A + (long long)row * lda + kt + cv);
            *(float2*)&As2[cv + 0][2 * row] = make_float2(a.x, a.x);
            *(float2*)&As2[cv + 1][2 * row] = make_float2(a.y, a.y);
            *(float2*)&As2[cv + 2][2 * row] = make_float2(a.z, a.z);
            *(float2*)&As2[cv + 3][2 * row] = make_float2(a.w, a.w);
            // B tile (direct: Bs[k][n])
            int brow = L >> 5;
            int bcol = (L & 31) * 4;
            float4 b = *(const float4*)(B + (long long)(kt + brow) * ldb + bcol);
            *(float4*)&Bs[brow][bcol] = b;
        }
        __syncthreads();
        #pragma unroll
        for (int k = 0; k < 16; k++) {
            unsigned long long aa[8], bb[4];
            ulonglong2 t0 = *(const ulonglong2*)&As2[k][ty * 16];
            ulonglong2 t1 = *(const ulonglong2*)&As2[k][ty * 16 + 4];
            ulonglong2 t2 = *(const ulonglong2*)&As2[k][ty * 16 + 8];
            ulonglong2 t3 = *(const ulonglong2*)&As2[k][ty * 16 + 12];
            aa[0] = t0.x; aa[1] = t0.y; aa[2] = t1.x; aa[3] = t1.y;
            aa[4] = t2.x; aa[5] = t2.y; aa[6] = t3.x; aa[7] = t3.y;
            ulonglong2 u0 = *(const ulonglong2*)&Bs[k][tx * 8];
            ulonglong2 u1 = *(const ulonglong2*)&Bs[k][tx * 8 + 4];
            bb[0] = u0.x; bb[1] = u0.y; bb[2] = u1.x; bb[3] = u1.y;
            #pragma unroll
            for (int i = 0; i < 8; i++)
                #pragma unroll
                for (int j = 0; j < 4; j++)
                    fma2(acc2[i][j], aa[i], bb[j]);
        }
        __syncthreads();
    }

    #pragma unroll
    for (int i = 0; i < 8; i++) {
        ulonglong2 o0, o1;
        o0.x = acc2[i][0]; o0.y = acc2[i][1];
        o1.x = acc2[i][2]; o1.y = acc2[i][3];
        float* cr = C + (long long)(ty * 8 + i) * ldc + tx * 8;
        *(ulonglong2*)(cr)     = o0;
        *(ulonglong2*)(cr + 4) = o1;
    }
}

// ---------------------------------------------------------------------------
// RoPE in place on Q and K. One thread per (row, head, j<64) pair.
// ---------------------------------------------------------------------------
__global__ __launch_bounds__(256) void rope_kernel(float* __restrict__ Q,
                                                   float* __restrict__ K)
{
    int idx = blockIdx.x * blockDim.x + threadIdx.x;
    if (idx >= ROWS * NH * 64) return;
    int j   = idx & 63;
    int h   = (idx >> 6) & (NH - 1);
    int row = idx >> 10;
    int s   = row & (SEQ - 1);

    float invf = powf(10000.0f, -(float)j * (1.0f / 64.0f));
    float ang  = (float)s * invf;
    float c = cosf(ang), sn = sinf(ang);

    long long base = (long long)row * HIDDEN + h * HD + j;
    float q0 = Q[base], q1 = Q[base + 64];
    Q[base]      = q0 * c - q1 * sn;
    Q[base + 64] = q1 * c + q0 * sn;
    float k0 = K[base], k1 = K[base + 64];
    K[base]      = k0 * c - k1 * sn;
    K[base + 64] = k1 * c + k0 * sn;
}

// ---------------------------------------------------------------------------
// Row softmax in place. One block per row of length SEQ (2048).
// ---------------------------------------------------------------------------
__global__ __launch_bounds__(256) void softmax_rows(float* __restrict__ S)
{
    __shared__ float red[8];
    long long row = blockIdx.x;
    float* p = S + row * SEQ;
    int tid = threadIdx.x;
    int lane = tid & 31, wid = tid >> 5;

    float v[8];
    float4 x0 = *(const float4*)(p + tid * 8);
    float4 x1 = *(const float4*)(p + tid * 8 + 4);
    v[0] = x0.x; v[1] = x0.y; v[2] = x0.z; v[3] = x0.w;
    v[4] = x1.x; v[5] = x1.y; v[6] = x1.z; v[7] = x1.w;

    float m = v[0];
    #pragma unroll
    for (int i = 1; i < 8; i++) m = fmaxf(m, v[i]);
    #pragma unroll
    for (int o = 16; o; o >>= 1) m = fmaxf(m, __shfl_xor_sync(0xFFFFFFFFu, m, o));
    if (lane == 0) red[wid] = m;
    __syncthreads();
    m = red[0];
    #pragma unroll
    for (int i = 1; i < 8; i++) m = fmaxf(m, red[i]);
    __syncthreads();

    float sum = 0.0f;
    #pragma unroll
    for (int i = 0; i < 8; i++) { v[i] = expf(v[i] - m); sum += v[i]; }
    #pragma unroll
    for (int o = 16; o; o >>= 1) sum += __shfl_xor_sync(0xFFFFFFFFu, sum, o);
    if (lane == 0) red[wid] = sum;
    __syncthreads();
    sum = 0.0f;
    #pragma unroll
    for (int i = 0; i < 8; i++) sum += red[i];
    float inv = 1.0f / sum;

    float4 y0, y1;
    y0.x = v[0] * inv; y0.y = v[1] * inv; y0.z = v[2] * inv; y0.w = v[3] * inv;
    y1.x = v[4] * inv; y1.y = v[5] * inv; y1.z = v[6] * inv; y1.w = v[7] * inv;
    *(float4*)(p + tid * 8)     = y0;
    *(float4*)(p + tid * 8 + 4) = y1;
}

// ---------------------------------------------------------------------------
extern "C" void kernel_launch(void* const* d_in, const int* in_sizes, int n_in,
                              void* d_out, int out_size)
{
    const float* X  = (const float*)d_in[0];
    const float* Wq = (const float*)d_in[1];
    const float* Wk = (const float*)d_in[2];
    const float* Wv = (const float*)d_in[3];
    const float* Wo = (const float*)d_in[4];
    float* out = (float*)d_out;

    float *Q, *K, *V, *CTX, *S;
    cudaGetSymbolAddress((void**)&Q,   g_Q);
    cudaGetSymbolAddress((void**)&K,   g_K);
    cudaGetSymbolAddress((void**)&V,   g_V);
    cudaGetSymbolAddress((void**)&CTX, g_ctx);
    cudaGetSymbolAddress((void**)&S,   g_S);

    const long long SH  = (long long)SEQ * HIDDEN;     // batch stride of Q/K/V/ctx
    const long long SS  = (long long)SEQ * SEQ;        // per-(b,h) scores stride
    const float scale = 0.08838834764831845f;          // 1/sqrt(128)

    dim3 blk(256);

    // QKV projections: [4096,2048] @ W^T
    dim3 gproj(HIDDEN / 128, ROWS / 128, 1);
    gemm_nt<<<gproj, blk>>>(X, HIDDEN, 0, 0, Wq, HIDDEN, 0, 0,
                            Q, HIDDEN, 0, 0, HIDDEN, 1.0f);
    gemm_nt<<<gproj, blk>>>(X, HIDDEN, 0, 0, Wk, HIDDEN, 0, 0,
                            K, HIDDEN, 0, 0, HIDDEN, 1.0f);
    gemm_nt<<<gproj, blk>>>(X, HIDDEN, 0, 0, Wv, HIDDEN, 0, 0,
                            V, HIDDEN, 0, 0, HIDDEN, 1.0f);

    // RoPE on Q and K
    rope_kernel<<<(ROWS * NH * 64) / 256, blk>>>(Q, K);

    // scores[b,h] = scale * Q_bh @ K_bh^T   (K=128), z = b*16+h
    dim3 gsc(SEQ / 128, SEQ / 128, BATCH * NH);
    gemm_nt<<<gsc, blk>>>(Q, HIDDEN, SH, HD,
                          K, HIDDEN, SH, HD,
                          S, SEQ, 16 * SS, SS,
                          HD, scale);

    // softmax rows in place
    softmax_rows<<<BATCH * NH * SEQ, blk>>>(S);

    // ctx[b,h] = P_bh @ V_bh   (M=2048, N=128, K=2048)
    dim3 gpv(HD / 128, SEQ / 128, BATCH * NH);
    gemm_nn<<<gpv, blk>>>(S, SEQ, 16 * SS, SS,
                          V, HIDDEN, SH, HD,
                          CTX, HIDDEN, SH, HD,
                          SEQ);

    // output projection: ctx @ Wo^T -> out
    gemm_nt<<<gproj, blk>>>(CTX, HIDDEN, 0, 0, Wo, HIDDEN, 0, 0,
                            out, HIDDEN, 0, 0, HIDDEN, 1.0f);
}

// round 6
// speedup vs baseline: 1.6486x; 1.6486x over previous
#include <cuda_runtime.h>
#include <cuda_bf16.h>
#include <cstdint>
#include <math.h>

#define HIDDEN 2048
#define NH 16
#define HD 128
#define BATCH 2
#define SEQ 2048
#define ROWS (BATCH*SEQ)   /* 4096 */

typedef __nv_bfloat16 bf16;

// ---------------------------------------------------------------------------
// Scratch (allocation-free: __device__ globals)
// ---------------------------------------------------------------------------
__device__ float g_Q[ROWS * HIDDEN];
__device__ float g_K[ROWS * HIDDEN];
__device__ float g_V[ROWS * HIDDEN];
__device__ float g_ctx[ROWS * HIDDEN];
__device__ float g_S[134217728];                    /* 32*2048*2048 scores */

__device__ bf16 g_Xh[ROWS * HIDDEN],  g_Xl[ROWS * HIDDEN];
__device__ bf16 g_Wqh[HIDDEN*HIDDEN], g_Wql[HIDDEN*HIDDEN];
__device__ bf16 g_Wkh[HIDDEN*HIDDEN], g_Wkl[HIDDEN*HIDDEN];
__device__ bf16 g_Wvh[HIDDEN*HIDDEN], g_Wvl[HIDDEN*HIDDEN];
__device__ bf16 g_Woh[HIDDEN*HIDDEN], g_Wol[HIDDEN*HIDDEN];
__device__ bf16 g_Qh[ROWS * HIDDEN],  g_Ql[ROWS * HIDDEN];
__device__ bf16 g_Kh[ROWS * HIDDEN],  g_Kl[ROWS * HIDDEN];
__device__ bf16 g_Vth[ROWS * HIDDEN], g_Vtl[ROWS * HIDDEN];   /* V^T per head */
__device__ bf16 g_Ph[134217728],      g_Pl[134217728];        /* probs hi/lo */
__device__ bf16 g_ch[ROWS * HIDDEN],  g_cl[ROWS * HIDDEN];

// ---------------------------------------------------------------------------
__device__ __forceinline__ uint32_t smem_u32(const void* p) {
    uint32_t a;
    asm("{ .reg .u64 t; cvta.to.shared.u64 t, %1; cvt.u32.u64 %0, t; }"
        : "=r"(a) : "l"(p));
    return a;
}

__device__ __forceinline__ void cp_async16(uint32_t s, const void* g) {
    asm volatile("cp.async.cg.shared.global [%0], [%1], 16;\n"
                 :: "r"(s), "l"(g) : "memory");
}
#define CP_COMMIT()  asm volatile("cp.async.commit_group;\n" ::: "memory")
#define CP_WAIT_1()  asm volatile("cp.async.wait_group 1;\n" ::: "memory")
#define CP_WAIT_0()  asm volatile("cp.async.wait_group 0;\n" ::: "memory")

#define LDSM4(r, a) \
    asm volatile("ldmatrix.sync.aligned.m8n8.x4.shared.b16 {%0,%1,%2,%3}, [%4];" \
        : "=r"((r)[0]), "=r"((r)[1]), "=r"((r)[2]), "=r"((r)[3]) : "r"(a))

#define MMA_BF16(c, a, b0, b1) \
    asm volatile("mma.sync.aligned.m16n8k16.row.col.f32.bf16.bf16.f32 " \
        "{%0,%1,%2,%3},{%4,%5,%6,%7},{%8,%9},{%0,%1,%2,%3};" \
        : "+f"((c)[0]), "+f"((c)[1]), "+f"((c)[2]), "+f"((c)[3]) \
        : "r"((a)[0]), "r"((a)[1]), "r"((a)[2]), "r"((a)[3]), "r"(b0), "r"(b1))

// ---------------------------------------------------------------------------
// Split-fp32 tensor-core GEMM:  C[M,N] = alpha * A[M,K] @ B[N,K]^T
// A,B given as bf16 (hi,lo) pairs, K-contiguous. 128x128 CTA tile, BK=32,
// cp.async double buffer, 8 warps (warp tile 64x32), mma.sync m16n8k16,
// 3-term emulation: Ah*Bh + Ah*Bl + Al*Bh into fp32 accumulators.
// z -> (z>>4)*s?B + (z&15)*s?H batch indexing.
// ---------------------------------------------------------------------------
#define SMS 40                    /* smem row stride in bf16 (80B, 16B-mult) */
#define TILE_E (128*SMS)          /* 5120 bf16 per tile */
#define BUF_E  (4*TILE_E)         /* Ah|Al|Bh|Bl */
#define SMEM_BYTES (2*BUF_E*2)    /* 81920 */

__global__ __launch_bounds__(256) void mma_nt(
    const bf16* __restrict__ Ah, const bf16* __restrict__ Al,
    int lda, long long saB, long long saH,
    const bf16* __restrict__ Bh, const bf16* __restrict__ Bl,
    int ldb, long long sbB, long long sbH,
    float* __restrict__ C, int ldc, long long scB, long long scH,
    int K, float alpha)
{
    extern __shared__ bf16 sm[];
    const uint32_t s0 = smem_u32(sm);
    const int tid = threadIdx.x;
    const int wid = tid >> 5, lane = tid & 31;

    const int z = blockIdx.z;
    const long long zb = z >> 4, zh = z & 15;
    const long long aoff = zb * saB + zh * saH + (long long)blockIdx.y * 128 * lda;
    const long long boff = zb * sbB + zh * sbH + (long long)blockIdx.x * 128 * ldb;
    Ah += aoff; Al += aoff;
    Bh += boff; Bl += boff;
    C  += zb * scB + zh * scH + (long long)blockIdx.y * 128 * ldc
                              + (long long)blockIdx.x * 128;

    const bf16* srcs[4] = {Ah, Al, Bh, Bl};
    const int ldt[4] = {lda, lda, ldb, ldb};

    // global->smem load coords: thread covers 2 16B-chunks per tile
    const int lrow = tid >> 1;           // 0..127
    const int lc0  = (tid & 1) * 2;      // chunk 0/2

    // ldmatrix per-lane offsets
    const int wm = (wid >> 2) << 6;      // 0 / 64
    const int wn = (wid & 3) << 5;       // 0/32/64/96
    const int i8 = lane & 7, msel = lane >> 3;
    const int a_row = i8 + ((msel & 1) << 3);
    const int a_k   = (msel >> 1) << 3;
    const int b_row = i8 + ((msel >> 1) << 3);
    const int b_k   = (msel & 1) << 3;

    float acc[4][4][4];
    #pragma unroll
    for (int i = 0; i < 4; i++)
        #pragma unroll
        for (int j = 0; j < 4; j++)
            #pragma unroll
            for (int r = 0; r < 4; r++) acc[i][j][r] = 0.0f;

    const int NC = K >> 5;

    // issue chunk c into buffer c&1
    auto issue = [&](int c) {
        const int kt = c << 5;
        const uint32_t dbuf = s0 + (uint32_t)((c & 1) * BUF_E) * 2;
        #pragma unroll
        for (int t = 0; t < 4; t++) {
            const bf16* g = srcs[t] + (long long)lrow * ldt[t] + kt;
            const uint32_t db = dbuf + (uint32_t)(t * TILE_E + lrow * SMS) * 2;
            cp_async16(db + lc0 * 16,        g + lc0 * 8);
            cp_async16(db + (lc0 + 1) * 16,  g + (lc0 + 1) * 8);
        }
        CP_COMMIT();
    };

    issue(0);

    for (int c = 0; c < NC; c++) {
        if (c + 1 < NC) { issue(c + 1); CP_WAIT_1(); }
        else            { CP_WAIT_0(); }
        __syncthreads();

        const uint32_t B0  = s0 + (uint32_t)((c & 1) * BUF_E) * 2;
        const uint32_t bAh = B0;
        const uint32_t bAl = B0 + TILE_E * 2;
        const uint32_t bBh = B0 + 2 * TILE_E * 2;
        const uint32_t bBl = B0 + 3 * TILE_E * 2;

        #pragma unroll
        for (int k16 = 0; k16 < 32; k16 += 16) {
            uint32_t af[4][4], bhf[2][4], blf[2][4];
            #pragma unroll
            for (int mi = 0; mi < 4; mi++)
                LDSM4(af[mi], bAh + (uint32_t)(((wm + mi * 16 + a_row) * SMS)
                                               + k16 + a_k) * 2);
            #pragma unroll
            for (int ni = 0; ni < 2; ni++)
                LDSM4(bhf[ni], bBh + (uint32_t)(((wn + ni * 16 + b_row) * SMS)
                                                + k16 + b_k) * 2);
            #pragma unroll
            for (int mi = 0; mi < 4; mi++)
                #pragma unroll
                for (int nj = 0; nj < 4; nj++)
                    MMA_BF16(acc[mi][nj], af[mi],
                             bhf[nj >> 1][(nj & 1) * 2], bhf[nj >> 1][(nj & 1) * 2 + 1]);
            #pragma unroll
            for (int ni = 0; ni < 2; ni++)
                LDSM4(blf[ni], bBl + (uint32_t)(((wn + ni * 16 + b_row) * SMS)
                                                + k16 + b_k) * 2);
            #pragma unroll
            for (int mi = 0; mi < 4; mi++)
                #pragma unroll
                for (int nj = 0; nj < 4; nj++)
                    MMA_BF16(acc[mi][nj], af[mi],
                             blf[nj >> 1][(nj & 1) * 2], blf[nj >> 1][(nj & 1) * 2 + 1]);
            #pragma unroll
            for (int mi = 0; mi < 4; mi++)
                LDSM4(af[mi], bAl + (uint32_t)(((wm + mi * 16 + a_row) * SMS)
                                               + k16 + a_k) * 2);
            #pragma unroll
            for (int mi = 0; mi < 4; mi++)
                #pragma unroll
                for (int nj = 0; nj < 4; nj++)
                    MMA_BF16(acc[mi][nj], af[mi],
                             bhf[nj >> 1][(nj & 1) * 2], bhf[nj >> 1][(nj & 1) * 2 + 1]);
        }
        __syncthreads();
    }

    // Epilogue: fragment layout -> C
    const int gr = lane >> 2, tc = (lane & 3) * 2;
    #pragma unroll
    for (int mi = 0; mi < 4; mi++) {
        const int row0 = wm + mi * 16 + gr;
        #pragma unroll
        for (int nj = 0; nj < 4; nj++) {
            const int col = wn + nj * 8 + tc;
            float2 lo, hi;
            lo.x = alpha * acc[mi][nj][0]; lo.y = alpha * acc[mi][nj][1];
            hi.x = alpha * acc[mi][nj][2]; hi.y = alpha * acc[mi][nj][3];
            *(float2*)(C + (long long)row0 * ldc + col)       = lo;
            *(float2*)(C + (long long)(row0 + 8) * ldc + col) = hi;
        }
    }
}

// ---------------------------------------------------------------------------
// fp32 -> (hi, lo) bf16 split
// ---------------------------------------------------------------------------
__device__ __forceinline__ void split2(float x, bf16& h, bf16& l) {
    h = __float2bfloat16(x);
    l = __float2bfloat16(x - __bfloat162float(h));
}

__global__ __launch_bounds__(256) void cvt_hilo(const float* __restrict__ src,
                                                bf16* __restrict__ h,
                                                bf16* __restrict__ l, int n4)
{
    int i = blockIdx.x * 256 + threadIdx.x;
    if (i >= n4) return;
    float4 x = *(const float4*)(src + i * 4);
    bf16 h0, h1, h2, h3, l0, l1, l2, l3;
    split2(x.x, h0, l0); split2(x.y, h1, l1);
    split2(x.z, h2, l2); split2(x.w, h3, l3);
    *(__nv_bfloat162*)(h + i * 4)     = __nv_bfloat162(h0, h1);
    *(__nv_bfloat162*)(h + i * 4 + 2) = __nv_bfloat162(h2, h3);
    *(__nv_bfloat162*)(l + i * 4)     = __nv_bfloat162(l0, l1);
    *(__nv_bfloat162*)(l + i * 4 + 2) = __nv_bfloat162(l2, l3);
}

// ---------------------------------------------------------------------------
// RoPE on Q,K (f32 in) -> bf16 hi/lo out. One thread per (row, head, j<64).
// ---------------------------------------------------------------------------
__global__ __launch_bounds__(256) void rope_cvt(
    const float* __restrict__ Q, const float* __restrict__ K,
    bf16* __restrict__ Qh, bf16* __restrict__ Ql,
    bf16* __restrict__ Kh, bf16* __restrict__ Kl)
{
    int idx = blockIdx.x * 256 + threadIdx.x;
    int j   = idx & 63;
    int h   = (idx >> 6) & (NH - 1);
    int row = idx >> 10;
    int s   = row & (SEQ - 1);

    float invf = powf(10000.0f, -(float)j * (1.0f / 64.0f));
    float ang  = (float)s * invf;
    float c = cosf(ang), sn = sinf(ang);

    long long base = (long long)row * HIDDEN + h * HD + j;
    float q0 = Q[base], q1 = Q[base + 64];
    float k0 = K[base], k1 = K[base + 64];
    float qa = q0 * c - q1 * sn, qb = q1 * c + q0 * sn;
    float ka = k0 * c - k1 * sn, kb = k1 * c + k0 * sn;

    bf16 hh, ll;
    split2(qa, hh, ll); Qh[base] = hh;      Ql[base] = ll;
    split2(qb, hh, ll); Qh[base + 64] = hh; Ql[base + 64] = ll;
    split2(ka, hh, ll); Kh[base] = hh;      Kl[base] = ll;
    split2(kb, hh, ll); Kh[base + 64] = hh; Kl[base + 64] = ll;
}

// ---------------------------------------------------------------------------
// Per-head transpose-convert of V: Vt[(z*128+d)*SEQ + s] = V[(b*SEQ+s)*H + h*128+d]
// ---------------------------------------------------------------------------
__global__ __launch_bounds__(256) void vtrans(const float* __restrict__ V,
                                              bf16* __restrict__ Vth,
                                              bf16* __restrict__ Vtl)
{
    __shared__ float t[32][33];
    int tx = threadIdx.x & 31, ty = threadIdx.x >> 5;   // 32x8
    int z = blockIdx.z, b = z >> 4, h = z & 15;
    int s0 = blockIdx.x * 32, d0 = blockIdx.y * 32;

    #pragma unroll
    for (int r = 0; r < 4; r++) {
        int s = s0 + ty + r * 8, d = d0 + tx;
        t[ty + r * 8][tx] = V[(long long)(b * SEQ + s) * HIDDEN + h * HD + d];
    }
    __syncthreads();
    #pragma unroll
    for (int r = 0; r < 4; r++) {
        int d = d0 + ty + r * 8, s = s0 + tx;
        float x = t[tx][ty + r * 8];
        bf16 hh, ll; split2(x, hh, ll);
        long long o = (long long)(z * HD + d) * SEQ + s;
        Vth[o] = hh; Vtl[o] = ll;
    }
}

// ---------------------------------------------------------------------------
// Row softmax: f32 scores in, bf16 hi/lo probs out. One block per row (2048).
// ---------------------------------------------------------------------------
__global__ __launch_bounds__(256) void softmax_rows(const float* __restrict__ S,
                                                    bf16* __restrict__ Ph,
                                                    bf16* __restrict__ Pl)
{
    __shared__ float red[8];
    long long row = blockIdx.x;
    const float* p = S + row * SEQ;
    int tid = threadIdx.x;
    int lane = tid & 31, wid = tid >> 5;

    float v[8];
    float4 x0 = *(const float4*)(p + tid * 8);
    float4 x1 = *(const float4*)(p + tid * 8 + 4);
    v[0] = x0.x; v[1] = x0.y; v[2] = x0.z; v[3] = x0.w;
    v[4] = x1.x; v[5] = x1.y; v[6] = x1.z; v[7] = x1.w;

    float m = v[0];
    #pragma unroll
    for (int i = 1; i < 8; i++) m = fmaxf(m, v[i]);
    #pragma unroll
    for (int o = 16; o; o >>= 1) m = fmaxf(m, __shfl_xor_sync(0xFFFFFFFFu, m, o));
    if (lane == 0) red[wid] = m;
    __syncthreads();
    m = red[0];
    #pragma unroll
    for (int i = 1; i < 8; i++) m = fmaxf(m, red[i]);
    __syncthreads();

    float sum = 0.0f;
    #pragma unroll
    for (int i = 0; i < 8; i++) { v[i] = expf(v[i] - m); sum += v[i]; }
    #pragma unroll
    for (int o = 16; o; o >>= 1) sum += __shfl_xor_sync(0xFFFFFFFFu, sum, o);
    if (lane == 0) red[wid] = sum;
    __syncthreads();
    sum = 0.0f;
    #pragma unroll
    for (int i = 0; i < 8; i++) sum += red[i];
    float inv = 1.0f / sum;

    bf16 h[8], l[8];
    #pragma unroll
    for (int i = 0; i < 8; i++) split2(v[i] * inv, h[i], l[i]);
    bf16* ph = Ph + row * SEQ + tid * 8;
    bf16* pl = Pl + row * SEQ + tid * 8;
    #pragma unroll
    for (int i = 0; i < 4; i++) {
        *(__nv_bfloat162*)(ph + 2 * i) = __nv_bfloat162(h[2 * i], h[2 * i + 1]);
        *(__nv_bfloat162*)(pl + 2 * i) = __nv_bfloat162(l[2 * i], l[2 * i + 1]);
    }
}

// ---------------------------------------------------------------------------
extern "C" void kernel_launch(void* const* d_in, const int* in_sizes, int n_in,
                              void* d_out, int out_size)
{
    const float* X  = (const float*)d_in[0];
    const float* Wq = (const float*)d_in[1];
    const float* Wk = (const float*)d_in[2];
    const float* Wv = (const float*)d_in[3];
    const float* Wo = (const float*)d_in[4];
    float* out = (float*)d_out;

    float *Q, *K, *V, *CTX, *S;
    bf16 *Xh, *Xl, *Wqh, *Wql, *Wkh, *Wkl, *Wvh, *Wvl, *Woh, *Wol;
    bf16 *Qh, *Ql, *Kh, *Kl, *Vth, *Vtl, *Ph, *Pl, *Ch, *Cl;
    cudaGetSymbolAddress((void**)&Q,   g_Q);
    cudaGetSymbolAddress((void**)&K,   g_K);
    cudaGetSymbolAddress((void**)&V,   g_V);
    cudaGetSymbolAddress((void**)&CTX, g_ctx);
    cudaGetSymbolAddress((void**)&S,   g_S);
    cudaGetSymbolAddress((void**)&Xh,  g_Xh);  cudaGetSymbolAddress((void**)&Xl,  g_Xl);
    cudaGetSymbolAddress((void**)&Wqh, g_Wqh); cudaGetSymbolAddress((void**)&Wql, g_Wql);
    cudaGetSymbolAddress((void**)&Wkh, g_Wkh); cudaGetSymbolAddress((void**)&Wkl, g_Wkl);
    cudaGetSymbolAddress((void**)&Wvh, g_Wvh); cudaGetSymbolAddress((void**)&Wvl, g_Wvl);
    cudaGetSymbolAddress((void**)&Woh, g_Woh); cudaGetSymbolAddress((void**)&Wol, g_Wol);
    cudaGetSymbolAddress((void**)&Qh,  g_Qh);  cudaGetSymbolAddress((void**)&Ql,  g_Ql);
    cudaGetSymbolAddress((void**)&Kh,  g_Kh);  cudaGetSymbolAddress((void**)&Kl,  g_Kl);
    cudaGetSymbolAddress((void**)&Vth, g_Vth); cudaGetSymbolAddress((void**)&Vtl, g_Vtl);
    cudaGetSymbolAddress((void**)&Ph,  g_Ph);  cudaGetSymbolAddress((void**)&Pl,  g_Pl);
    cudaGetSymbolAddress((void**)&Ch,  g_ch);  cudaGetSymbolAddress((void**)&Cl,  g_cl);

    cudaFuncSetAttribute(mma_nt, cudaFuncAttributeMaxDynamicSharedMemorySize,
                         SMEM_BYTES);

    const long long SH = (long long)SEQ * HIDDEN;   // batch stride Q/K/V/ctx
    const long long SS = (long long)SEQ * SEQ;      // per-(b,h) scores stride
    const long long VZ = (long long)HD * SEQ;       // per-(b,h) Vt stride
    const float scale = 0.08838834764831845f;       // 1/sqrt(128)

    dim3 blk(256);

    // Convert inputs to bf16 hi/lo
    cvt_hilo<<<(ROWS * HIDDEN / 4 + 255) / 256, blk>>>(X,  Xh,  Xl,  ROWS * HIDDEN / 4);
    cvt_hilo<<<(HIDDEN * HIDDEN / 4 + 255) / 256, blk>>>(Wq, Wqh, Wql, HIDDEN * HIDDEN / 4);
    cvt_hilo<<<(HIDDEN * HIDDEN / 4 + 255) / 256, blk>>>(Wk, Wkh, Wkl, HIDDEN * HIDDEN / 4);
    cvt_hilo<<<(HIDDEN * HIDDEN / 4 + 255) / 256, blk>>>(Wv, Wvh, Wvl, HIDDEN * HIDDEN / 4);
    cvt_hilo<<<(HIDDEN * HIDDEN / 4 + 255) / 256, blk>>>(Wo, Woh, Wol, HIDDEN * HIDDEN / 4);

    // QKV projections -> f32
    dim3 gproj(HIDDEN / 128, ROWS / 128, 1);
    mma_nt<<<gproj, blk, SMEM_BYTES>>>(Xh, Xl, HIDDEN, 0, 0,
                                       Wqh, Wql, HIDDEN, 0, 0,
                                       Q, HIDDEN, 0, 0, HIDDEN, 1.0f);
    mma_nt<<<gproj, blk, SMEM_BYTES>>>(Xh, Xl, HIDDEN, 0, 0,
                                       Wkh, Wkl, HIDDEN, 0, 0,
                                       K, HIDDEN, 0, 0, HIDDEN, 1.0f);
    mma_nt<<<gproj, blk, SMEM_BYTES>>>(Xh, Xl, HIDDEN, 0, 0,
                                       Wvh, Wvl, HIDDEN, 0, 0,
                                       V, HIDDEN, 0, 0, HIDDEN, 1.0f);

    // RoPE + convert Q,K ; transpose-convert V
    rope_cvt<<<(ROWS * NH * 64) / 256, blk>>>(Q, K, Qh, Ql, Kh, Kl);
    vtrans<<<dim3(SEQ / 32, HD / 32, BATCH * NH), blk>>>(V, Vth, Vtl);

    // scores = scale * Q @ K^T  per (b,h)
    dim3 gsc(SEQ / 128, SEQ / 128, BATCH * NH);
    mma_nt<<<gsc, blk, SMEM_BYTES>>>(Qh, Ql, HIDDEN, SH, HD,
                                     Kh, Kl, HIDDEN, SH, HD,
                                     S, SEQ, 16 * SS, SS, HD, scale);

    // softmax -> bf16 hi/lo probs
    softmax_rows<<<BATCH * NH * SEQ, blk>>>(S, Ph, Pl);

    // ctx = P @ V  per (b,h)   (Vt is [d][s] K-major)
    dim3 gpv(HD / 128, SEQ / 128, BATCH * NH);
    mma_nt<<<gpv, blk, SMEM_BYTES>>>(Ph, Pl, SEQ, 16 * SS, SS,
                                     Vth, Vtl, SEQ, 16 * VZ, VZ,
                                     CTX, HIDDEN, SH, HD, SEQ, 1.0f);

    // output projection
    cvt_hilo<<<(ROWS * HIDDEN / 4 + 255) / 256, blk>>>(CTX, Ch, Cl, ROWS * HIDDEN / 4);
    mma_nt<<<gproj, blk, SMEM_BYTES>>>(Ch, Cl, HIDDEN, 0, 0,
                                       Woh, Wol, HIDDEN, 0, 0,
                                       out, HIDDEN, 0, 0, HIDDEN, 1.0f);
}

// round 7
// speedup vs baseline: 2.7728x; 1.6819x over previous
#include <cuda_runtime.h>
#include <cuda_bf16.h>
#include <cstdint>
#include <math.h>

#define HIDDEN 2048
#define NH 16
#define HD 128
#define BATCH 2
#define SEQ 2048
#define ROWS (BATCH*SEQ)   /* 4096 */

typedef __nv_bfloat16 bf16;

// ---------------------------------------------------------------------------
// Scratch (allocation-free: __device__ globals)
// ---------------------------------------------------------------------------
__device__ float g_Q[ROWS * HIDDEN];
__device__ float g_K[ROWS * HIDDEN];
__device__ float g_V[ROWS * HIDDEN];
__device__ float g_ctx[ROWS * HIDDEN];

__device__ bf16 g_Xh[ROWS * HIDDEN],  g_Xl[ROWS * HIDDEN];
__device__ bf16 g_Wqh[HIDDEN*HIDDEN], g_Wql[HIDDEN*HIDDEN];
__device__ bf16 g_Wkh[HIDDEN*HIDDEN], g_Wkl[HIDDEN*HIDDEN];
__device__ bf16 g_Wvh[HIDDEN*HIDDEN], g_Wvl[HIDDEN*HIDDEN];
__device__ bf16 g_Woh[HIDDEN*HIDDEN], g_Wol[HIDDEN*HIDDEN];
__device__ bf16 g_Qh[ROWS * HIDDEN],  g_Ql[ROWS * HIDDEN];
__device__ bf16 g_Kh[ROWS * HIDDEN],  g_Kl[ROWS * HIDDEN];
__device__ bf16 g_Vth[ROWS * HIDDEN], g_Vtl[ROWS * HIDDEN];   /* V^T per head */
__device__ bf16 g_ch[ROWS * HIDDEN],  g_cl[ROWS * HIDDEN];

// ---------------------------------------------------------------------------
__device__ __forceinline__ uint32_t smem_u32(const void* p) {
    uint32_t a;
    asm("{ .reg .u64 t; cvta.to.shared.u64 t, %1; cvt.u32.u64 %0, t; }"
        : "=r"(a) : "l"(p));
    return a;
}

__device__ __forceinline__ void cp_async16(uint32_t s, const void* g) {
    asm volatile("cp.async.cg.shared.global [%0], [%1], 16;\n"
                 :: "r"(s), "l"(g) : "memory");
}
#define CP_COMMIT()  asm volatile("cp.async.commit_group;\n" ::: "memory")
#define CP_WAIT_1()  asm volatile("cp.async.wait_group 1;\n" ::: "memory")
#define CP_WAIT_0()  asm volatile("cp.async.wait_group 0;\n" ::: "memory")

#define LDSM4(r, a) \
    asm volatile("ldmatrix.sync.aligned.m8n8.x4.shared.b16 {%0,%1,%2,%3}, [%4];" \
        : "=r"((r)[0]), "=r"((r)[1]), "=r"((r)[2]), "=r"((r)[3]) : "r"(a))

#define MMA_BF16(c, a, b0, b1) \
    asm volatile("mma.sync.aligned.m16n8k16.row.col.f32.bf16.bf16.f32 " \
        "{%0,%1,%2,%3},{%4,%5,%6,%7},{%8,%9},{%0,%1,%2,%3};" \
        : "+f"((c)[0]), "+f"((c)[1]), "+f"((c)[2]), "+f"((c)[3]) \
        : "r"((a)[0]), "r"((a)[1]), "r"((a)[2]), "r"((a)[3]), "r"(b0), "r"(b1))

__device__ __forceinline__ uint32_t pack_bf2(float x, float y) {
    __nv_bfloat162 t = __float22bfloat162_rn(make_float2(x, y));
    return *(uint32_t*)&t;
}
__device__ __forceinline__ float bf_hi(float x) {
    return __bfloat162float(__float2bfloat16(x));
}

// ---------------------------------------------------------------------------
// Split-fp32 tensor-core GEMM:  C[M,N] = alpha * A[M,K] @ B[N,K]^T
// (used for the 4 projections; unchanged from R6)
// ---------------------------------------------------------------------------
#define SMS 40
#define TILE_E (128*SMS)
#define BUF_E  (4*TILE_E)
#define SMEM_BYTES (2*BUF_E*2)

__global__ __launch_bounds__(256) void mma_nt(
    const bf16* __restrict__ Ah, const bf16* __restrict__ Al,
    int lda, long long saB, long long saH,
    const bf16* __restrict__ Bh, const bf16* __restrict__ Bl,
    int ldb, long long sbB, long long sbH,
    float* __restrict__ C, int ldc, long long scB, long long scH,
    int K, float alpha)
{
    extern __shared__ bf16 sm[];
    const uint32_t s0 = smem_u32(sm);
    const int tid = threadIdx.x;
    const int wid = tid >> 5, lane = tid & 31;

    const int z = blockIdx.z;
    const long long zb = z >> 4, zh = z & 15;
    const long long aoff = zb * saB + zh * saH + (long long)blockIdx.y * 128 * lda;
    const long long boff = zb * sbB + zh * sbH + (long long)blockIdx.x * 128 * ldb;
    Ah += aoff; Al += aoff;
    Bh += boff; Bl += boff;
    C  += zb * scB + zh * scH + (long long)blockIdx.y * 128 * ldc
                              + (long long)blockIdx.x * 128;

    const bf16* srcs[4] = {Ah, Al, Bh, Bl};
    const int ldt[4] = {lda, lda, ldb, ldb};

    const int lrow = tid >> 1;
    const int lc0  = (tid & 1) * 2;

    const int wm = (wid >> 2) << 6;
    const int wn = (wid & 3) << 5;
    const int i8 = lane & 7, msel = lane >> 3;
    const int a_row = i8 + ((msel & 1) << 3);
    const int a_k   = (msel >> 1) << 3;
    const int b_row = i8 + ((msel >> 1) << 3);
    const int b_k   = (msel & 1) << 3;

    float acc[4][4][4];
    #pragma unroll
    for (int i = 0; i < 4; i++)
        #pragma unroll
        for (int j = 0; j < 4; j++)
            #pragma unroll
            for (int r = 0; r < 4; r++) acc[i][j][r] = 0.0f;

    const int NC = K >> 5;

    auto issue = [&](int c) {
        const int kt = c << 5;
        const uint32_t dbuf = s0 + (uint32_t)((c & 1) * BUF_E) * 2;
        #pragma unroll
        for (int t = 0; t < 4; t++) {
            const bf16* g = srcs[t] + (long long)lrow * ldt[t] + kt;
            const uint32_t db = dbuf + (uint32_t)(t * TILE_E + lrow * SMS) * 2;
            cp_async16(db + lc0 * 16,        g + lc0 * 8);
            cp_async16(db + (lc0 + 1) * 16,  g + (lc0 + 1) * 8);
        }
        CP_COMMIT();
    };

    issue(0);

    for (int c = 0; c < NC; c++) {
        if (c + 1 < NC) { issue(c + 1); CP_WAIT_1(); }
        else            { CP_WAIT_0(); }
        __syncthreads();

        const uint32_t B0  = s0 + (uint32_t)((c & 1) * BUF_E) * 2;
        const uint32_t bAh = B0;
        const uint32_t bAl = B0 + TILE_E * 2;
        const uint32_t bBh = B0 + 2 * TILE_E * 2;
        const uint32_t bBl = B0 + 3 * TILE_E * 2;

        #pragma unroll
        for (int k16 = 0; k16 < 32; k16 += 16) {
            uint32_t af[4][4], bhf[2][4], blf[2][4];
            #pragma unroll
            for (int mi = 0; mi < 4; mi++)
                LDSM4(af[mi], bAh + (uint32_t)(((wm + mi * 16 + a_row) * SMS)
                                               + k16 + a_k) * 2);
            #pragma unroll
            for (int ni = 0; ni < 2; ni++)
                LDSM4(bhf[ni], bBh + (uint32_t)(((wn + ni * 16 + b_row) * SMS)
                                                + k16 + b_k) * 2);
            #pragma unroll
            for (int mi = 0; mi < 4; mi++)
                #pragma unroll
                for (int nj = 0; nj < 4; nj++)
                    MMA_BF16(acc[mi][nj], af[mi],
                             bhf[nj >> 1][(nj & 1) * 2], bhf[nj >> 1][(nj & 1) * 2 + 1]);
            #pragma unroll
            for (int ni = 0; ni < 2; ni++)
                LDSM4(blf[ni], bBl + (uint32_t)(((wn + ni * 16 + b_row) * SMS)
                                                + k16 + b_k) * 2);
            #pragma unroll
            for (int mi = 0; mi < 4; mi++)
                #pragma unroll
                for (int nj = 0; nj < 4; nj++)
                    MMA_BF16(acc[mi][nj], af[mi],
                             blf[nj >> 1][(nj & 1) * 2], blf[nj >> 1][(nj & 1) * 2 + 1]);
            #pragma unroll
            for (int mi = 0; mi < 4; mi++)
                LDSM4(af[mi], bAl + (uint32_t)(((wm + mi * 16 + a_row) * SMS)
                                               + k16 + a_k) * 2);
            #pragma unroll
            for (int mi = 0; mi < 4; mi++)
                #pragma unroll
                for (int nj = 0; nj < 4; nj++)
                    MMA_BF16(acc[mi][nj], af[mi],
                             bhf[nj >> 1][(nj & 1) * 2], bhf[nj >> 1][(nj & 1) * 2 + 1]);
        }
        __syncthreads();
    }

    const int gr = lane >> 2, tc = (lane & 3) * 2;
    #pragma unroll
    for (int mi = 0; mi < 4; mi++) {
        const int row0 = wm + mi * 16 + gr;
        #pragma unroll
        for (int nj = 0; nj < 4; nj++) {
            const int col = wn + nj * 8 + tc;
            float2 lo, hi;
            lo.x = alpha * acc[mi][nj][0]; lo.y = alpha * acc[mi][nj][1];
            hi.x = alpha * acc[mi][nj][2]; hi.y = alpha * acc[mi][nj][3];
            *(float2*)(C + (long long)row0 * ldc + col)       = lo;
            *(float2*)(C + (long long)(row0 + 8) * ldc + col) = hi;
        }
    }
}

// ---------------------------------------------------------------------------
// Fused flash attention: per CTA = (128 q-rows, one (b,h)).
// 8 warps; warp w owns q-rows [16w,16w+16) x all 128 key-cols.
// S = Q@K^T (3-term split-bf16, fp32 acc) -> online softmax -> P@V with
// P A-fragments packed straight from S accumulator fragments.
// Q scaled by 1/sqrt(HD) at rope_cvt time.
// ---------------------------------------------------------------------------
#define FSTR 136                  /* smem row stride (bf16), 272B */
#define FTS  (128*FSTR)           /* elems per tile */
#define FLASH_SMEM (6*FTS*2)      /* 208896 B */

__global__ __launch_bounds__(256, 1) void flash_attn(
    const bf16* __restrict__ Qh_, const bf16* __restrict__ Ql_,
    const bf16* __restrict__ Kh_, const bf16* __restrict__ Kl_,
    const bf16* __restrict__ Vh_, const bf16* __restrict__ Vl_,
    float* __restrict__ CTX)
{
    extern __shared__ bf16 sm[];
    const uint32_t s0 = smem_u32(sm);
    const uint32_t sQh = s0,             sQl = s0 + FTS * 2;
    const uint32_t sKh = s0 + 2*FTS*2,   sKl = s0 + 3*FTS*2;
    const uint32_t sVh = s0 + 4*FTS*2,   sVl = s0 + 5*FTS*2;

    const int tid = threadIdx.x, wid = tid >> 5, lane = tid & 31;
    const int z = blockIdx.y, b = z >> 4, h = z & 15;
    const int q0 = blockIdx.x * 128;
    const long long SH = (long long)SEQ * HIDDEN;

    const bf16* qh  = Qh_ + (long long)b * SH + h * HD + (long long)q0 * HIDDEN;
    const bf16* ql  = Ql_ + (long long)b * SH + h * HD + (long long)q0 * HIDDEN;
    const bf16* kh0 = Kh_ + (long long)b * SH + h * HD;
    const bf16* kl0 = Kl_ + (long long)b * SH + h * HD;
    const bf16* vh0 = Vh_ + (long long)z * HD * SEQ;
    const bf16* vl0 = Vl_ + (long long)z * HD * SEQ;

    const int lrow = tid >> 1, lc0 = (tid & 1) * 8;
    auto ldtile = [&](const bf16* g, int ldg, uint32_t dst) {
        const bf16* gr = g + (long long)lrow * ldg + lc0 * 8;
        uint32_t ds = dst + (uint32_t)(lrow * 272 + lc0 * 16);
        #pragma unroll
        for (int i = 0; i < 8; i++) cp_async16(ds + i * 16, gr + i * 8);
    };

    // Q tile resident for whole kernel
    ldtile(qh, HIDDEN, sQh);
    ldtile(ql, HIDDEN, sQl);

    const int i8 = lane & 7, msel = lane >> 3;
    const int a_row = i8 + ((msel & 1) << 3);
    const int a_k   = (msel >> 1) << 3;
    const int b_row = i8 + ((msel >> 1) << 3);
    const int b_k   = (msel & 1) << 3;
    const int wm = wid << 4;

    float o[16][4];
    #pragma unroll
    for (int t = 0; t < 16; t++)
        #pragma unroll
        for (int r = 0; r < 4; r++) o[t][r] = 0.0f;
    float m0 = -1e30f, m1 = -1e30f, l0 = 0.0f, l1 = 0.0f;

    for (int kt = 0; kt < 16; kt++) {
        const int kb = kt << 7;
        __syncthreads();                 // previous iter's reads done
        ldtile(kh0 + (long long)kb * HIDDEN, HIDDEN, sKh);
        ldtile(kl0 + (long long)kb * HIDDEN, HIDDEN, sKl);
        ldtile(vh0 + kb, SEQ, sVh);
        ldtile(vl0 + kb, SEQ, sVl);
        CP_COMMIT(); CP_WAIT_0();
        __syncthreads();

        // ---- S = Q @ K^T (scaled), 3-term ----
        float c[16][4];
        #pragma unroll
        for (int t = 0; t < 16; t++)
            #pragma unroll
            for (int r = 0; r < 4; r++) c[t][r] = 0.0f;

        #pragma unroll
        for (int k16 = 0; k16 < 128; k16 += 16) {
            uint32_t ah[4], al[4];
            LDSM4(ah, sQh + (uint32_t)(((wm + a_row) * FSTR) + k16 + a_k) * 2);
            LDSM4(al, sQl + (uint32_t)(((wm + a_row) * FSTR) + k16 + a_k) * 2);
            #pragma unroll
            for (int g = 0; g < 8; g++) {
                uint32_t bh[4], bl[4];
                LDSM4(bh, sKh + (uint32_t)((((g << 4) + b_row) * FSTR) + k16 + b_k) * 2);
                LDSM4(bl, sKl + (uint32_t)((((g << 4) + b_row) * FSTR) + k16 + b_k) * 2);
                #pragma unroll
                for (int hf = 0; hf < 2; hf++) {
                    const int t = (g << 1) + hf;
                    MMA_BF16(c[t], ah, bh[hf * 2], bh[hf * 2 + 1]);
                    MMA_BF16(c[t], ah, bl[hf * 2], bl[hf * 2 + 1]);
                    MMA_BF16(c[t], al, bh[hf * 2], bh[hf * 2 + 1]);
                }
            }
        }

        // ---- online softmax ----
        float mx0 = c[0][0], mx1 = c[0][2];
        #pragma unroll
        for (int t = 0; t < 16; t++) {
            mx0 = fmaxf(mx0, fmaxf(c[t][0], c[t][1]));
            mx1 = fmaxf(mx1, fmaxf(c[t][2], c[t][3]));
        }
        mx0 = fmaxf(mx0, __shfl_xor_sync(0xFFFFFFFFu, mx0, 1));
        mx0 = fmaxf(mx0, __shfl_xor_sync(0xFFFFFFFFu, mx0, 2));
        mx1 = fmaxf(mx1, __shfl_xor_sync(0xFFFFFFFFu, mx1, 1));
        mx1 = fmaxf(mx1, __shfl_xor_sync(0xFFFFFFFFu, mx1, 2));
        const float nm0 = fmaxf(m0, mx0), nm1 = fmaxf(m1, mx1);
        const float al0 = __expf(m0 - nm0), al1 = __expf(m1 - nm1);
        m0 = nm0; m1 = nm1;

        float s0s = 0.0f, s1s = 0.0f;
        #pragma unroll
        for (int t = 0; t < 16; t++) {
            c[t][0] = __expf(c[t][0] - m0);
            c[t][1] = __expf(c[t][1] - m0);
            c[t][2] = __expf(c[t][2] - m1);
            c[t][3] = __expf(c[t][3] - m1);
            s0s += c[t][0] + c[t][1];
            s1s += c[t][2] + c[t][3];
        }
        s0s += __shfl_xor_sync(0xFFFFFFFFu, s0s, 1);
        s0s += __shfl_xor_sync(0xFFFFFFFFu, s0s, 2);
        s1s += __shfl_xor_sync(0xFFFFFFFFu, s1s, 1);
        s1s += __shfl_xor_sync(0xFFFFFFFFu, s1s, 2);
        l0 = l0 * al0 + s0s;
        l1 = l1 * al1 + s1s;

        #pragma unroll
        for (int t = 0; t < 16; t++) {
            o[t][0] *= al0; o[t][1] *= al0;
            o[t][2] *= al1; o[t][3] *= al1;
        }

        // ---- O += P @ V (3-term; P frags from registers) ----
        #pragma unroll
        for (int j = 0; j < 8; j++) {
            const float p00 = c[2*j][0],   p01 = c[2*j][1];
            const float p02 = c[2*j][2],   p03 = c[2*j][3];
            const float p10 = c[2*j+1][0], p11 = c[2*j+1][1];
            const float p12 = c[2*j+1][2], p13 = c[2*j+1][3];
            uint32_t ph[4], pl[4];
            ph[0] = pack_bf2(p00, p01);
            ph[1] = pack_bf2(p02, p03);
            ph[2] = pack_bf2(p10, p11);
            ph[3] = pack_bf2(p12, p13);
            pl[0] = pack_bf2(p00 - bf_hi(p00), p01 - bf_hi(p01));
            pl[1] = pack_bf2(p02 - bf_hi(p02), p03 - bf_hi(p03));
            pl[2] = pack_bf2(p10 - bf_hi(p10), p11 - bf_hi(p11));
            pl[3] = pack_bf2(p12 - bf_hi(p12), p13 - bf_hi(p13));
            #pragma unroll
            for (int g = 0; g < 8; g++) {
                uint32_t vh[4], vl[4];
                LDSM4(vh, sVh + (uint32_t)((((g << 4) + b_row) * FSTR) + (j << 4) + b_k) * 2);
                LDSM4(vl, sVl + (uint32_t)((((g << 4) + b_row) * FSTR) + (j << 4) + b_k) * 2);
                #pragma unroll
                for (int hf = 0; hf < 2; hf++) {
                    const int t = (g << 1) + hf;
                    MMA_BF16(o[t], ph, vh[hf * 2], vh[hf * 2 + 1]);
                    MMA_BF16(o[t], ph, vl[hf * 2], vl[hf * 2 + 1]);
                    MMA_BF16(o[t], pl, vh[hf * 2], vh[hf * 2 + 1]);
                }
            }
        }
    }

    // ---- epilogue: O /= l, write ctx ----
    const float i0 = 1.0f / l0, i1 = 1.0f / l1;
    const int r0 = q0 + wm + (lane >> 2);
    const int tc = (lane & 3) * 2;
    float* c0p = CTX + (long long)(b * SEQ + r0) * HIDDEN + h * HD;
    float* c1p = c0p + 8 * HIDDEN;
    #pragma unroll
    for (int t = 0; t < 16; t++) {
        const int col = t * 8 + tc;
        *(float2*)(c0p + col) = make_float2(o[t][0] * i0, o[t][1] * i0);
        *(float2*)(c1p + col) = make_float2(o[t][2] * i1, o[t][3] * i1);
    }
}

// ---------------------------------------------------------------------------
// fp32 -> (hi, lo) bf16 split helpers
// ---------------------------------------------------------------------------
__device__ __forceinline__ void split2(float x, bf16& h, bf16& l) {
    h = __float2bfloat16(x);
    l = __float2bfloat16(x - __bfloat162float(h));
}

__global__ __launch_bounds__(256) void cvt_hilo(const float* __restrict__ src,
                                                bf16* __restrict__ h,
                                                bf16* __restrict__ l, int n4)
{
    int i = blockIdx.x * 256 + threadIdx.x;
    if (i >= n4) return;
    float4 x = *(const float4*)(src + i * 4);
    bf16 h0, h1, h2, h3, l0, l1, l2, l3;
    split2(x.x, h0, l0); split2(x.y, h1, l1);
    split2(x.z, h2, l2); split2(x.w, h3, l3);
    *(__nv_bfloat162*)(h + i * 4)     = __nv_bfloat162(h0, h1);
    *(__nv_bfloat162*)(h + i * 4 + 2) = __nv_bfloat162(h2, h3);
    *(__nv_bfloat162*)(l + i * 4)     = __nv_bfloat162(l0, l1);
    *(__nv_bfloat162*)(l + i * 4 + 2) = __nv_bfloat162(l2, l3);
}

// ---------------------------------------------------------------------------
// RoPE on Q,K (f32 in) -> bf16 hi/lo out; Q pre-scaled by 1/sqrt(HD).
// ---------------------------------------------------------------------------
__global__ __launch_bounds__(256) void rope_cvt(
    const float* __restrict__ Q, const float* __restrict__ K,
    bf16* __restrict__ Qh, bf16* __restrict__ Ql,
    bf16* __restrict__ Kh, bf16* __restrict__ Kl)
{
    int idx = blockIdx.x * 256 + threadIdx.x;
    int j   = idx & 63;
    int h   = (idx >> 6) & (NH - 1);
    int row = idx >> 10;
    int s   = row & (SEQ - 1);

    const float scale = 0.08838834764831845f;   /* 1/sqrt(128) */
    float invf = powf(10000.0f, -(float)j * (1.0f / 64.0f));
    float ang  = (float)s * invf;
    float c = cosf(ang), sn = sinf(ang);

    long long base = (long long)row * HIDDEN + h * HD + j;
    float q0 = Q[base], q1 = Q[base + 64];
    float k0 = K[base], k1 = K[base + 64];
    float qa = (q0 * c - q1 * sn) * scale, qb = (q1 * c + q0 * sn) * scale;
    float ka = k0 * c - k1 * sn, kb = k1 * c + k0 * sn;

    bf16 hh, ll;
    split2(qa, hh, ll); Qh[base] = hh;      Ql[base] = ll;
    split2(qb, hh, ll); Qh[base + 64] = hh; Ql[base + 64] = ll;
    split2(ka, hh, ll); Kh[base] = hh;      Kl[base] = ll;
    split2(kb, hh, ll); Kh[base + 64] = hh; Kl[base + 64] = ll;
}

// ---------------------------------------------------------------------------
// Per-head transpose-convert of V: Vt[(z*128+d)*SEQ + s] = V[(b*SEQ+s)*H + h*128+d]
// ---------------------------------------------------------------------------
__global__ __launch_bounds__(256) void vtrans(const float* __restrict__ V,
                                              bf16* __restrict__ Vth,
                                              bf16* __restrict__ Vtl)
{
    __shared__ float t[32][33];
    int tx = threadIdx.x & 31, ty = threadIdx.x >> 5;
    int z = blockIdx.z, b = z >> 4, h = z & 15;
    int s0 = blockIdx.x * 32, d0 = blockIdx.y * 32;

    #pragma unroll
    for (int r = 0; r < 4; r++) {
        int s = s0 + ty + r * 8, d = d0 + tx;
        t[ty + r * 8][tx] = V[(long long)(b * SEQ + s) * HIDDEN + h * HD + d];
    }
    __syncthreads();
    #pragma unroll
    for (int r = 0; r < 4; r++) {
        int d = d0 + ty + r * 8, s = s0 + tx;
        float x = t[tx][ty + r * 8];
        bf16 hh, ll; split2(x, hh, ll);
        long long o = (long long)(z * HD + d) * SEQ + s;
        Vth[o] = hh; Vtl[o] = ll;
    }
}

// ---------------------------------------------------------------------------
extern "C" void kernel_launch(void* const* d_in, const int* in_sizes, int n_in,
                              void* d_out, int out_size)
{
    const float* X  = (const float*)d_in[0];
    const float* Wq = (const float*)d_in[1];
    const float* Wk = (const float*)d_in[2];
    const float* Wv = (const float*)d_in[3];
    const float* Wo = (const float*)d_in[4];
    float* out = (float*)d_out;

    float *Q, *K, *V, *CTX;
    bf16 *Xh, *Xl, *Wqh, *Wql, *Wkh, *Wkl, *Wvh, *Wvl, *Woh, *Wol;
    bf16 *Qh, *Ql, *Kh, *Kl, *Vth, *Vtl, *Ch, *Cl;
    cudaGetSymbolAddress((void**)&Q,   g_Q);
    cudaGetSymbolAddress((void**)&K,   g_K);
    cudaGetSymbolAddress((void**)&V,   g_V);
    cudaGetSymbolAddress((void**)&CTX, g_ctx);
    cudaGetSymbolAddress((void**)&Xh,  g_Xh);  cudaGetSymbolAddress((void**)&Xl,  g_Xl);
    cudaGetSymbolAddress((void**)&Wqh, g_Wqh); cudaGetSymbolAddress((void**)&Wql, g_Wql);
    cudaGetSymbolAddress((void**)&Wkh, g_Wkh); cudaGetSymbolAddress((void**)&Wkl, g_Wkl);
    cudaGetSymbolAddress((void**)&Wvh, g_Wvh); cudaGetSymbolAddress((void**)&Wvl, g_Wvl);
    cudaGetSymbolAddress((void**)&Woh, g_Woh); cudaGetSymbolAddress((void**)&Wol, g_Wol);
    cudaGetSymbolAddress((void**)&Qh,  g_Qh);  cudaGetSymbolAddress((void**)&Ql,  g_Ql);
    cudaGetSymbolAddress((void**)&Kh,  g_Kh);  cudaGetSymbolAddress((void**)&Kl,  g_Kl);
    cudaGetSymbolAddress((void**)&Vth, g_Vth); cudaGetSymbolAddress((void**)&Vtl, g_Vtl);
    cudaGetSymbolAddress((void**)&Ch,  g_ch);  cudaGetSymbolAddress((void**)&Cl,  g_cl);

    cudaFuncSetAttribute(mma_nt, cudaFuncAttributeMaxDynamicSharedMemorySize,
                         SMEM_BYTES);
    cudaFuncSetAttribute(flash_attn, cudaFuncAttributeMaxDynamicSharedMemorySize,
                         FLASH_SMEM);

    dim3 blk(256);

    // Convert inputs to bf16 hi/lo
    cvt_hilo<<<(ROWS * HIDDEN / 4 + 255) / 256, blk>>>(X,  Xh,  Xl,  ROWS * HIDDEN / 4);
    cvt_hilo<<<(HIDDEN * HIDDEN / 4 + 255) / 256, blk>>>(Wq, Wqh, Wql, HIDDEN * HIDDEN / 4);
    cvt_hilo<<<(HIDDEN * HIDDEN / 4 + 255) / 256, blk>>>(Wk, Wkh, Wkl, HIDDEN * HIDDEN / 4);
    cvt_hilo<<<(HIDDEN * HIDDEN / 4 + 255) / 256, blk>>>(Wv, Wvh, Wvl, HIDDEN * HIDDEN / 4);
    cvt_hilo<<<(HIDDEN * HIDDEN / 4 + 255) / 256, blk>>>(Wo, Woh, Wol, HIDDEN * HIDDEN / 4);

    // QKV projections -> f32
    dim3 gproj(HIDDEN / 128, ROWS / 128, 1);
    mma_nt<<<gproj, blk, SMEM_BYTES>>>(Xh, Xl, HIDDEN, 0, 0,
                                       Wqh, Wql, HIDDEN, 0, 0,
                                       Q, HIDDEN, 0, 0, HIDDEN, 1.0f);
    mma_nt<<<gproj, blk, SMEM_BYTES>>>(Xh, Xl, HIDDEN, 0, 0,
                                       Wkh, Wkl, HIDDEN, 0, 0,
                                       K, HIDDEN, 0, 0, HIDDEN, 1.0f);
    mma_nt<<<gproj, blk, SMEM_BYTES>>>(Xh, Xl, HIDDEN, 0, 0,
                                       Wvh, Wvl, HIDDEN, 0, 0,
                                       V, HIDDEN, 0, 0, HIDDEN, 1.0f);

    // RoPE + convert Q,K (Q pre-scaled) ; transpose-convert V
    rope_cvt<<<(ROWS * NH * 64) / 256, blk>>>(Q, K, Qh, Ql, Kh, Kl);
    vtrans<<<dim3(SEQ / 32, HD / 32, BATCH * NH), blk>>>(V, Vth, Vtl);

    // Fused attention: scores + softmax + P@V
    flash_attn<<<dim3(SEQ / 128, BATCH * NH), blk, FLASH_SMEM>>>(
        Qh, Ql, Kh, Kl, Vth, Vtl, CTX);

    // output projection
    cvt_hilo<<<(ROWS * HIDDEN / 4 + 255) / 256, blk>>>(CTX, Ch, Cl, ROWS * HIDDEN / 4);
    mma_nt<<<gproj, blk, SMEM_BYTES>>>(Ch, Cl, HIDDEN, 0, 0,
                                       Woh, Wol, HIDDEN, 0, 0,
                                       out, HIDDEN, 0, 0, HIDDEN, 1.0f);
}

// round 8
// speedup vs baseline: 2.8682x; 1.0344x over previous
#include <cuda_runtime.h>
#include <cuda_bf16.h>
#include <cstdint>
#include <math.h>

#define HIDDEN 2048
#define NH 16
#define HD 128
#define BATCH 2
#define SEQ 2048
#define ROWS (BATCH*SEQ)   /* 4096 */

typedef __nv_bfloat16 bf16;

// ---------------------------------------------------------------------------
// Scratch (allocation-free: __device__ globals)
// ---------------------------------------------------------------------------
__device__ float g_Q[ROWS * HIDDEN];
__device__ float g_K[ROWS * HIDDEN];
__device__ float g_V[ROWS * HIDDEN];
__device__ float g_ctx[ROWS * HIDDEN];

__device__ bf16 g_Xh[ROWS * HIDDEN],  g_Xl[ROWS * HIDDEN];
__device__ bf16 g_Wqh[HIDDEN*HIDDEN], g_Wql[HIDDEN*HIDDEN];
__device__ bf16 g_Wkh[HIDDEN*HIDDEN], g_Wkl[HIDDEN*HIDDEN];
__device__ bf16 g_Wvh[HIDDEN*HIDDEN], g_Wvl[HIDDEN*HIDDEN];
__device__ bf16 g_Woh[HIDDEN*HIDDEN], g_Wol[HIDDEN*HIDDEN];
__device__ bf16 g_Qh[ROWS * HIDDEN],  g_Ql[ROWS * HIDDEN];
__device__ bf16 g_Kh[ROWS * HIDDEN],  g_Kl[ROWS * HIDDEN];
__device__ bf16 g_Vth[ROWS * HIDDEN], g_Vtl[ROWS * HIDDEN];   /* V^T per head */
__device__ bf16 g_ch[ROWS * HIDDEN],  g_cl[ROWS * HIDDEN];

// ---------------------------------------------------------------------------
__device__ __forceinline__ uint32_t smem_u32(const void* p) {
    uint32_t a;
    asm("{ .reg .u64 t; cvta.to.shared.u64 t, %1; cvt.u32.u64 %0, t; }"
        : "=r"(a) : "l"(p));
    return a;
}

__device__ __forceinline__ void cp_async16(uint32_t s, const void* g) {
    asm volatile("cp.async.cg.shared.global [%0], [%1], 16;\n"
                 :: "r"(s), "l"(g) : "memory");
}
#define CP_COMMIT()  asm volatile("cp.async.commit_group;\n" ::: "memory")
#define CP_WAIT_1()  asm volatile("cp.async.wait_group 1;\n" ::: "memory")
#define CP_WAIT_0()  asm volatile("cp.async.wait_group 0;\n" ::: "memory")

#define LDSM4(r, a) \
    asm volatile("ldmatrix.sync.aligned.m8n8.x4.shared.b16 {%0,%1,%2,%3}, [%4];" \
        : "=r"((r)[0]), "=r"((r)[1]), "=r"((r)[2]), "=r"((r)[3]) : "r"(a))

#define MMA_BF16(c, a, b0, b1) \
    asm volatile("mma.sync.aligned.m16n8k16.row.col.f32.bf16.bf16.f32 " \
        "{%0,%1,%2,%3},{%4,%5,%6,%7},{%8,%9},{%0,%1,%2,%3};" \
        : "+f"((c)[0]), "+f"((c)[1]), "+f"((c)[2]), "+f"((c)[3]) \
        : "r"((a)[0]), "r"((a)[1]), "r"((a)[2]), "r"((a)[3]), "r"(b0), "r"(b1))

__device__ __forceinline__ uint32_t pack_bf2(float x, float y) {
    __nv_bfloat162 t = __float22bfloat162_rn(make_float2(x, y));
    return *(uint32_t*)&t;
}
__device__ __forceinline__ float bf_hi(float x) {
    return __bfloat162float(__float2bfloat16(x));
}

// ---------------------------------------------------------------------------
// Split-fp32 tensor-core GEMM:  C[M,N] = alpha * A[M,K] @ B[N,K]^T
// (projections; unchanged from R7)
// ---------------------------------------------------------------------------
#define SMS 40
#define TILE_E (128*SMS)
#define BUF_E  (4*TILE_E)
#define SMEM_BYTES (2*BUF_E*2)

__global__ __launch_bounds__(256) void mma_nt(
    const bf16* __restrict__ Ah, const bf16* __restrict__ Al,
    int lda, long long saB, long long saH,
    const bf16* __restrict__ Bh, const bf16* __restrict__ Bl,
    int ldb, long long sbB, long long sbH,
    float* __restrict__ C, int ldc, long long scB, long long scH,
    int K, float alpha)
{
    extern __shared__ bf16 sm[];
    const uint32_t s0 = smem_u32(sm);
    const int tid = threadIdx.x;
    const int wid = tid >> 5, lane = tid & 31;

    const int z = blockIdx.z;
    const long long zb = z >> 4, zh = z & 15;
    const long long aoff = zb * saB + zh * saH + (long long)blockIdx.y * 128 * lda;
    const long long boff = zb * sbB + zh * sbH + (long long)blockIdx.x * 128 * ldb;
    Ah += aoff; Al += aoff;
    Bh += boff; Bl += boff;
    C  += zb * scB + zh * scH + (long long)blockIdx.y * 128 * ldc
                              + (long long)blockIdx.x * 128;

    const bf16* srcs[4] = {Ah, Al, Bh, Bl};
    const int ldt[4] = {lda, lda, ldb, ldb};

    const int lrow = tid >> 1;
    const int lc0  = (tid & 1) * 2;

    const int wm = (wid >> 2) << 6;
    const int wn = (wid & 3) << 5;
    const int i8 = lane & 7, msel = lane >> 3;
    const int a_row = i8 + ((msel & 1) << 3);
    const int a_k   = (msel >> 1) << 3;
    const int b_row = i8 + ((msel >> 1) << 3);
    const int b_k   = (msel & 1) << 3;

    float acc[4][4][4];
    #pragma unroll
    for (int i = 0; i < 4; i++)
        #pragma unroll
        for (int j = 0; j < 4; j++)
            #pragma unroll
            for (int r = 0; r < 4; r++) acc[i][j][r] = 0.0f;

    const int NC = K >> 5;

    auto issue = [&](int c) {
        const int kt = c << 5;
        const uint32_t dbuf = s0 + (uint32_t)((c & 1) * BUF_E) * 2;
        #pragma unroll
        for (int t = 0; t < 4; t++) {
            const bf16* g = srcs[t] + (long long)lrow * ldt[t] + kt;
            const uint32_t db = dbuf + (uint32_t)(t * TILE_E + lrow * SMS) * 2;
            cp_async16(db + lc0 * 16,        g + lc0 * 8);
            cp_async16(db + (lc0 + 1) * 16,  g + (lc0 + 1) * 8);
        }
        CP_COMMIT();
    };

    issue(0);

    for (int c = 0; c < NC; c++) {
        if (c + 1 < NC) { issue(c + 1); CP_WAIT_1(); }
        else            { CP_WAIT_0(); }
        __syncthreads();

        const uint32_t B0  = s0 + (uint32_t)((c & 1) * BUF_E) * 2;
        const uint32_t bAh = B0;
        const uint32_t bAl = B0 + TILE_E * 2;
        const uint32_t bBh = B0 + 2 * TILE_E * 2;
        const uint32_t bBl = B0 + 3 * TILE_E * 2;

        #pragma unroll
        for (int k16 = 0; k16 < 32; k16 += 16) {
            uint32_t af[4][4], bhf[2][4], blf[2][4];
            #pragma unroll
            for (int mi = 0; mi < 4; mi++)
                LDSM4(af[mi], bAh + (uint32_t)(((wm + mi * 16 + a_row) * SMS)
                                               + k16 + a_k) * 2);
            #pragma unroll
            for (int ni = 0; ni < 2; ni++)
                LDSM4(bhf[ni], bBh + (uint32_t)(((wn + ni * 16 + b_row) * SMS)
                                                + k16 + b_k) * 2);
            #pragma unroll
            for (int mi = 0; mi < 4; mi++)
                #pragma unroll
                for (int nj = 0; nj < 4; nj++)
                    MMA_BF16(acc[mi][nj], af[mi],
                             bhf[nj >> 1][(nj & 1) * 2], bhf[nj >> 1][(nj & 1) * 2 + 1]);
            #pragma unroll
            for (int ni = 0; ni < 2; ni++)
                LDSM4(blf[ni], bBl + (uint32_t)(((wn + ni * 16 + b_row) * SMS)
                                                + k16 + b_k) * 2);
            #pragma unroll
            for (int mi = 0; mi < 4; mi++)
                #pragma unroll
                for (int nj = 0; nj < 4; nj++)
                    MMA_BF16(acc[mi][nj], af[mi],
                             blf[nj >> 1][(nj & 1) * 2], blf[nj >> 1][(nj & 1) * 2 + 1]);
            #pragma unroll
            for (int mi = 0; mi < 4; mi++)
                LDSM4(af[mi], bAl + (uint32_t)(((wm + mi * 16 + a_row) * SMS)
                                               + k16 + a_k) * 2);
            #pragma unroll
            for (int mi = 0; mi < 4; mi++)
                #pragma unroll
                for (int nj = 0; nj < 4; nj++)
                    MMA_BF16(acc[mi][nj], af[mi],
                             bhf[nj >> 1][(nj & 1) * 2], bhf[nj >> 1][(nj & 1) * 2 + 1]);
        }
        __syncthreads();
    }

    const int gr = lane >> 2, tc = (lane & 3) * 2;
    #pragma unroll
    for (int mi = 0; mi < 4; mi++) {
        const int row0 = wm + mi * 16 + gr;
        #pragma unroll
        for (int nj = 0; nj < 4; nj++) {
            const int col = wn + nj * 8 + tc;
            float2 lo, hi;
            lo.x = alpha * acc[mi][nj][0]; lo.y = alpha * acc[mi][nj][1];
            hi.x = alpha * acc[mi][nj][2]; hi.y = alpha * acc[mi][nj][3];
            *(float2*)(C + (long long)row0 * ldc + col)       = lo;
            *(float2*)(C + (long long)(row0 + 8) * ldc + col) = hi;
        }
    }
}

// ---------------------------------------------------------------------------
// Fused flash attention, double-buffered KV (64-key-row tiles).
// CTA = (128 q-rows, one (b,h)); warp w owns q-rows [16w,16w+16).
// ---------------------------------------------------------------------------
#define FSTR 136                  /* Q/K tile row stride (bf16) */
#define VSTR 72                   /* V tile row stride (bf16)   */
#define QTILE_B (128*FSTR*2)      /* 34816 */
#define KTILE_B (64*FSTR*2)       /* 17408 */
#define VTILE_B (128*VSTR*2)      /* 18432 */
#define OFF_Q 0
#define OFF_K (2*QTILE_B)         /* 69632  */
#define OFF_V (OFF_K + 4*KTILE_B) /* 139264 */
#define FLASH_SMEM (OFF_V + 4*VTILE_B)   /* 212992 */

__global__ __launch_bounds__(256, 1) void flash_attn(
    const bf16* __restrict__ Qh_, const bf16* __restrict__ Ql_,
    const bf16* __restrict__ Kh_, const bf16* __restrict__ Kl_,
    const bf16* __restrict__ Vh_, const bf16* __restrict__ Vl_,
    float* __restrict__ CTX)
{
    extern __shared__ bf16 sm[];
    const uint32_t s0 = smem_u32(sm);

    const int tid = threadIdx.x, wid = tid >> 5, lane = tid & 31;
    const int z = blockIdx.y, b = z >> 4, h = z & 15;
    const int q0 = blockIdx.x * 128;
    const long long SH = (long long)SEQ * HIDDEN;

    const bf16* qh  = Qh_ + (long long)b * SH + h * HD + (long long)q0 * HIDDEN;
    const bf16* ql  = Ql_ + (long long)b * SH + h * HD + (long long)q0 * HIDDEN;
    const bf16* kh0 = Kh_ + (long long)b * SH + h * HD;
    const bf16* kl0 = Kl_ + (long long)b * SH + h * HD;
    const bf16* vh0 = Vh_ + (long long)z * HD * SEQ;
    const bf16* vl0 = Vl_ + (long long)z * HD * SEQ;

    // ---- Q tile load (joined to stage-0 commit group) ----
    {
        const int lrow = tid >> 1, lc0 = (tid & 1) * 8;
        const bf16* gh = qh + (long long)lrow * HIDDEN + lc0 * 8;
        const bf16* gl = ql + (long long)lrow * HIDDEN + lc0 * 8;
        const uint32_t dh = s0 + OFF_Q + (uint32_t)(lrow * 272 + lc0 * 16);
        const uint32_t dl = dh + QTILE_B;
        #pragma unroll
        for (int i = 0; i < 8; i++) cp_async16(dh + i * 16, gh + i * 8);
        #pragma unroll
        for (int i = 0; i < 8; i++) cp_async16(dl + i * 16, gl + i * 8);
    }

    auto issueKV = [&](int kt) {
        const int st = kt & 1;
        const int kb = kt << 6;
        // K tiles: 64 rows x 128 cols
        {
            const int lrow = tid >> 2;          // 0..63
            const int lc   = (tid & 3) * 4;     // 4 chunks of 16B
            const bf16* gh = kh0 + (long long)(kb + lrow) * HIDDEN + lc * 8;
            const bf16* gl = kl0 + (long long)(kb + lrow) * HIDDEN + lc * 8;
            const uint32_t dh = s0 + OFF_K + (uint32_t)(st * 2 * KTILE_B
                                + lrow * 272 + lc * 16);
            const uint32_t dl = dh + KTILE_B;
            #pragma unroll
            for (int i = 0; i < 4; i++) cp_async16(dh + i * 16, gh + i * 8);
            #pragma unroll
            for (int i = 0; i < 4; i++) cp_async16(dl + i * 16, gl + i * 8);
        }
        // V tiles: 128 rows (d) x 64 cols (s)
        {
            const int lrow = tid >> 1;          // 0..127
            const int lc   = (tid & 1) * 4;     // 4 chunks
            const bf16* gh = vh0 + (long long)lrow * SEQ + kb + lc * 8;
            const bf16* gl = vl0 + (long long)lrow * SEQ + kb + lc * 8;
            const uint32_t dh = s0 + OFF_V + (uint32_t)(st * 2 * VTILE_B
                                + lrow * 144 + lc * 16);
            const uint32_t dl = dh + VTILE_B;
            #pragma unroll
            for (int i = 0; i < 4; i++) cp_async16(dh + i * 16, gh + i * 8);
            #pragma unroll
            for (int i = 0; i < 4; i++) cp_async16(dl + i * 16, gl + i * 8);
        }
        CP_COMMIT();
    };

    issueKV(0);      // group 0: Q + KV(0)

    const int i8 = lane & 7, msel = lane >> 3;
    const int a_row = i8 + ((msel & 1) << 3);
    const int a_k   = (msel >> 1) << 3;
    const int b_row = i8 + ((msel >> 1) << 3);
    const int b_k   = (msel & 1) << 3;
    const int wm = wid << 4;

    float o[16][4];
    #pragma unroll
    for (int t = 0; t < 16; t++)
        #pragma unroll
        for (int r = 0; r < 4; r++) o[t][r] = 0.0f;
    float m0 = -1e30f, m1 = -1e30f, l0 = 0.0f, l1 = 0.0f;

    const uint32_t bQh = s0 + OFF_Q, bQl = bQh + QTILE_B;

    for (int kt = 0; kt < 32; kt++) {
        if (kt + 1 < 32) { issueKV(kt + 1); CP_WAIT_1(); }
        else             { CP_WAIT_0(); }
        __syncthreads();

        const uint32_t bKh = s0 + OFF_K + (uint32_t)((kt & 1) * 2 * KTILE_B);
        const uint32_t bKl = bKh + KTILE_B;
        const uint32_t bVh = s0 + OFF_V + (uint32_t)((kt & 1) * 2 * VTILE_B);
        const uint32_t bVl = bVh + VTILE_B;

        // ---- S = Q @ K^T (scaled), 3-term; 16 q-rows x 64 k-cols ----
        float c[8][4];
        #pragma unroll
        for (int t = 0; t < 8; t++)
            #pragma unroll
            for (int r = 0; r < 4; r++) c[t][r] = 0.0f;

        #pragma unroll
        for (int k16 = 0; k16 < 128; k16 += 16) {
            uint32_t ah[4], al[4];
            LDSM4(ah, bQh + (uint32_t)(((wm + a_row) * FSTR) + k16 + a_k) * 2);
            LDSM4(al, bQl + (uint32_t)(((wm + a_row) * FSTR) + k16 + a_k) * 2);
            #pragma unroll
            for (int g = 0; g < 4; g++) {
                uint32_t bh[4], bl[4];
                LDSM4(bh, bKh + (uint32_t)((((g << 4) + b_row) * FSTR) + k16 + b_k) * 2);
                LDSM4(bl, bKl + (uint32_t)((((g << 4) + b_row) * FSTR) + k16 + b_k) * 2);
                #pragma unroll
                for (int hf = 0; hf < 2; hf++) {
                    const int t = (g << 1) + hf;
                    MMA_BF16(c[t], ah, bh[hf * 2], bh[hf * 2 + 1]);
                    MMA_BF16(c[t], ah, bl[hf * 2], bl[hf * 2 + 1]);
                    MMA_BF16(c[t], al, bh[hf * 2], bh[hf * 2 + 1]);
                }
            }
        }

        // ---- online softmax (rows lane>>2 and +8) ----
        float mx0 = c[0][0], mx1 = c[0][2];
        #pragma unroll
        for (int t = 0; t < 8; t++) {
            mx0 = fmaxf(mx0, fmaxf(c[t][0], c[t][1]));
            mx1 = fmaxf(mx1, fmaxf(c[t][2], c[t][3]));
        }
        mx0 = fmaxf(mx0, __shfl_xor_sync(0xFFFFFFFFu, mx0, 1));
        mx0 = fmaxf(mx0, __shfl_xor_sync(0xFFFFFFFFu, mx0, 2));
        mx1 = fmaxf(mx1, __shfl_xor_sync(0xFFFFFFFFu, mx1, 1));
        mx1 = fmaxf(mx1, __shfl_xor_sync(0xFFFFFFFFu, mx1, 2));
        const float nm0 = fmaxf(m0, mx0), nm1 = fmaxf(m1, mx1);
        const float al0 = __expf(m0 - nm0), al1 = __expf(m1 - nm1);
        m0 = nm0; m1 = nm1;

        float s0s = 0.0f, s1s = 0.0f;
        #pragma unroll
        for (int t = 0; t < 8; t++) {
            c[t][0] = __expf(c[t][0] - m0);
            c[t][1] = __expf(c[t][1] - m0);
            c[t][2] = __expf(c[t][2] - m1);
            c[t][3] = __expf(c[t][3] - m1);
            s0s += c[t][0] + c[t][1];
            s1s += c[t][2] + c[t][3];
        }
        s0s += __shfl_xor_sync(0xFFFFFFFFu, s0s, 1);
        s0s += __shfl_xor_sync(0xFFFFFFFFu, s0s, 2);
        s1s += __shfl_xor_sync(0xFFFFFFFFu, s1s, 1);
        s1s += __shfl_xor_sync(0xFFFFFFFFu, s1s, 2);
        l0 = l0 * al0 + s0s;
        l1 = l1 * al1 + s1s;

        #pragma unroll
        for (int t = 0; t < 16; t++) {
            o[t][0] *= al0; o[t][1] *= al0;
            o[t][2] *= al1; o[t][3] *= al1;
        }

        // ---- O += P @ V (3-term; P frags from registers) ----
        #pragma unroll
        for (int j = 0; j < 4; j++) {
            const float p00 = c[2*j][0],   p01 = c[2*j][1];
            const float p02 = c[2*j][2],   p03 = c[2*j][3];
            const float p10 = c[2*j+1][0], p11 = c[2*j+1][1];
            const float p12 = c[2*j+1][2], p13 = c[2*j+1][3];
            uint32_t ph[4], pl[4];
            ph[0] = pack_bf2(p00, p01);
            ph[1] = pack_bf2(p02, p03);
            ph[2] = pack_bf2(p10, p11);
            ph[3] = pack_bf2(p12, p13);
            pl[0] = pack_bf2(p00 - bf_hi(p00), p01 - bf_hi(p01));
            pl[1] = pack_bf2(p02 - bf_hi(p02), p03 - bf_hi(p03));
            pl[2] = pack_bf2(p10 - bf_hi(p10), p11 - bf_hi(p11));
            pl[3] = pack_bf2(p12 - bf_hi(p12), p13 - bf_hi(p13));
            #pragma unroll
            for (int g = 0; g < 8; g++) {
                uint32_t vh[4], vl[4];
                LDSM4(vh, bVh + (uint32_t)((((g << 4) + b_row) * VSTR) + (j << 4) + b_k) * 2);
                LDSM4(vl, bVl + (uint32_t)((((g << 4) + b_row) * VSTR) + (j << 4) + b_k) * 2);
                #pragma unroll
                for (int hf = 0; hf < 2; hf++) {
                    const int t = (g << 1) + hf;
                    MMA_BF16(o[t], ph, vh[hf * 2], vh[hf * 2 + 1]);
                    MMA_BF16(o[t], ph, vl[hf * 2], vl[hf * 2 + 1]);
                    MMA_BF16(o[t], pl, vh[hf * 2], vh[hf * 2 + 1]);
                }
            }
        }
        __syncthreads();
    }

    // ---- epilogue: O /= l, write ctx ----
    const float i0 = 1.0f / l0, i1 = 1.0f / l1;
    const int r0 = q0 + wm + (lane >> 2);
    const int tc = (lane & 3) * 2;
    float* c0p = CTX + (long long)(b * SEQ + r0) * HIDDEN + h * HD;
    float* c1p = c0p + 8 * HIDDEN;
    #pragma unroll
    for (int t = 0; t < 16; t++) {
        const int col = t * 8 + tc;
        *(float2*)(c0p + col) = make_float2(o[t][0] * i0, o[t][1] * i0);
        *(float2*)(c1p + col) = make_float2(o[t][2] * i1, o[t][3] * i1);
    }
}

// ---------------------------------------------------------------------------
// fp32 -> (hi, lo) bf16 split helpers
// ---------------------------------------------------------------------------
__device__ __forceinline__ void split2(float x, bf16& h, bf16& l) {
    h = __float2bfloat16(x);
    l = __float2bfloat16(x - __bfloat162float(h));
}

__global__ __launch_bounds__(256) void cvt_hilo(const float* __restrict__ src,
                                                bf16* __restrict__ h,
                                                bf16* __restrict__ l, int n4)
{
    int i = blockIdx.x * 256 + threadIdx.x;
    if (i >= n4) return;
    float4 x = *(const float4*)(src + i * 4);
    bf16 h0, h1, h2, h3, l0, l1, l2, l3;
    split2(x.x, h0, l0); split2(x.y, h1, l1);
    split2(x.z, h2, l2); split2(x.w, h3, l3);
    *(__nv_bfloat162*)(h + i * 4)     = __nv_bfloat162(h0, h1);
    *(__nv_bfloat162*)(h + i * 4 + 2) = __nv_bfloat162(h2, h3);
    *(__nv_bfloat162*)(l + i * 4)     = __nv_bfloat162(l0, l1);
    *(__nv_bfloat162*)(l + i * 4 + 2) = __nv_bfloat162(l2, l3);
}

// ---------------------------------------------------------------------------
// RoPE on Q,K (f32 in) -> bf16 hi/lo out; Q pre-scaled by 1/sqrt(HD).
// ---------------------------------------------------------------------------
__global__ __launch_bounds__(256) void rope_cvt(
    const float* __restrict__ Q, const float* __restrict__ K,
    bf16* __restrict__ Qh, bf16* __restrict__ Ql,
    bf16* __restrict__ Kh, bf16* __restrict__ Kl)
{
    int idx = blockIdx.x * 256 + threadIdx.x;
    int j   = idx & 63;
    int h   = (idx >> 6) & (NH - 1);
    int row = idx >> 10;
    int s   = row & (SEQ - 1);

    const float scale = 0.08838834764831845f;   /* 1/sqrt(128) */
    float invf = powf(10000.0f, -(float)j * (1.0f / 64.0f));
    float ang  = (float)s * invf;
    float c = cosf(ang), sn = sinf(ang);

    long long base = (long long)row * HIDDEN + h * HD + j;
    float q0 = Q[base], q1 = Q[base + 64];
    float k0 = K[base], k1 = K[base + 64];
    float qa = (q0 * c - q1 * sn) * scale, qb = (q1 * c + q0 * sn) * scale;
    float ka = k0 * c - k1 * sn, kb = k1 * c + k0 * sn;

    bf16 hh, ll;
    split2(qa, hh, ll); Qh[base] = hh;      Ql[base] = ll;
    split2(qb, hh, ll); Qh[base + 64] = hh; Ql[base + 64] = ll;
    split2(ka, hh, ll); Kh[base] = hh;      Kl[base] = ll;
    split2(kb, hh, ll); Kh[base + 64] = hh; Kl[base + 64] = ll;
}

// ---------------------------------------------------------------------------
// Per-head transpose-convert of V: Vt[(z*128+d)*SEQ + s] = V[(b*SEQ+s)*H + h*128+d]
// ---------------------------------------------------------------------------
__global__ __launch_bounds__(256) void vtrans(const float* __restrict__ V,
                                              bf16* __restrict__ Vth,
                                              bf16* __restrict__ Vtl)
{
    __shared__ float t[32][33];
    int tx = threadIdx.x & 31, ty = threadIdx.x >> 5;
    int z = blockIdx.z, b = z >> 4, h = z & 15;
    int s0 = blockIdx.x * 32, d0 = blockIdx.y * 32;

    #pragma unroll
    for (int r = 0; r < 4; r++) {
        int s = s0 + ty + r * 8, d = d0 + tx;
        t[ty + r * 8][tx] = V[(long long)(b * SEQ + s) * HIDDEN + h * HD + d];
    }
    __syncthreads();
    #pragma unroll
    for (int r = 0; r < 4; r++) {
        int d = d0 + ty + r * 8, s = s0 + tx;
        float x = t[tx][ty + r * 8];
        bf16 hh, ll; split2(x, hh, ll);
        long long o = (long long)(z * HD + d) * SEQ + s;
        Vth[o] = hh; Vtl[o] = ll;
    }
}

// ---------------------------------------------------------------------------
extern "C" void kernel_launch(void* const* d_in, const int* in_sizes, int n_in,
                              void* d_out, int out_size)
{
    const float* X  = (const float*)d_in[0];
    const float* Wq = (const float*)d_in[1];
    const float* Wk = (const float*)d_in[2];
    const float* Wv = (const float*)d_in[3];
    const float* Wo = (const float*)d_in[4];
    float* out = (float*)d_out;

    float *Q, *K, *V, *CTX;
    bf16 *Xh, *Xl, *Wqh, *Wql, *Wkh, *Wkl, *Wvh, *Wvl, *Woh, *Wol;
    bf16 *Qh, *Ql, *Kh, *Kl, *Vth, *Vtl, *Ch, *Cl;
    cudaGetSymbolAddress((void**)&Q,   g_Q);
    cudaGetSymbolAddress((void**)&K,   g_K);
    cudaGetSymbolAddress((void**)&V,   g_V);
    cudaGetSymbolAddress((void**)&CTX, g_ctx);
    cudaGetSymbolAddress((void**)&Xh,  g_Xh);  cudaGetSymbolAddress((void**)&Xl,  g_Xl);
    cudaGetSymbolAddress((void**)&Wqh, g_Wqh); cudaGetSymbolAddress((void**)&Wql, g_Wql);
    cudaGetSymbolAddress((void**)&Wkh, g_Wkh); cudaGetSymbolAddress((void**)&Wkl, g_Wkl);
    cudaGetSymbolAddress((void**)&Wvh, g_Wvh); cudaGetSymbolAddress((void**)&Wvl, g_Wvl);
    cudaGetSymbolAddress((void**)&Woh, g_Woh); cudaGetSymbolAddress((void**)&Wol, g_Wol);
    cudaGetSymbolAddress((void**)&Qh,  g_Qh);  cudaGetSymbolAddress((void**)&Ql,  g_Ql);
    cudaGetSymbolAddress((void**)&Kh,  g_Kh);  cudaGetSymbolAddress((void**)&Kl,  g_Kl);
    cudaGetSymbolAddress((void**)&Vth, g_Vth); cudaGetSymbolAddress((void**)&Vtl, g_Vtl);
    cudaGetSymbolAddress((void**)&Ch,  g_ch);  cudaGetSymbolAddress((void**)&Cl,  g_cl);

    cudaFuncSetAttribute(mma_nt, cudaFuncAttributeMaxDynamicSharedMemorySize,
                         SMEM_BYTES);
    cudaFuncSetAttribute(flash_attn, cudaFuncAttributeMaxDynamicSharedMemorySize,
                         FLASH_SMEM);

    dim3 blk(256);

    // Convert inputs to bf16 hi/lo
    cvt_hilo<<<(ROWS * HIDDEN / 4 + 255) / 256, blk>>>(X,  Xh,  Xl,  ROWS * HIDDEN / 4);
    cvt_hilo<<<(HIDDEN * HIDDEN / 4 + 255) / 256, blk>>>(Wq, Wqh, Wql, HIDDEN * HIDDEN / 4);
    cvt_hilo<<<(HIDDEN * HIDDEN / 4 + 255) / 256, blk>>>(Wk, Wkh, Wkl, HIDDEN * HIDDEN / 4);
    cvt_hilo<<<(HIDDEN * HIDDEN / 4 + 255) / 256, blk>>>(Wv, Wvh, Wvl, HIDDEN * HIDDEN / 4);
    cvt_hilo<<<(HIDDEN * HIDDEN / 4 + 255) / 256, blk>>>(Wo, Woh, Wol, HIDDEN * HIDDEN / 4);

    // QKV projections -> f32
    dim3 gproj(HIDDEN / 128, ROWS / 128, 1);
    mma_nt<<<gproj, blk, SMEM_BYTES>>>(Xh, Xl, HIDDEN, 0, 0,
                                       Wqh, Wql, HIDDEN, 0, 0,
                                       Q, HIDDEN, 0, 0, HIDDEN, 1.0f);
    mma_nt<<<gproj, blk, SMEM_BYTES>>>(Xh, Xl, HIDDEN, 0, 0,
                                       Wkh, Wkl, HIDDEN, 0, 0,
                                       K, HIDDEN, 0, 0, HIDDEN, 1.0f);
    mma_nt<<<gproj, blk, SMEM_BYTES>>>(Xh, Xl, HIDDEN, 0, 0,
                                       Wvh, Wvl, HIDDEN, 0, 0,
                                       V, HIDDEN, 0, 0, HIDDEN, 1.0f);

    // RoPE + convert Q,K (Q pre-scaled) ; transpose-convert V
    rope_cvt<<<(ROWS * NH * 64) / 256, blk>>>(Q, K, Qh, Ql, Kh, Kl);
    vtrans<<<dim3(SEQ / 32, HD / 32, BATCH * NH), blk>>>(V, Vth, Vtl);

    // Fused attention: scores + softmax + P@V (double-buffered KV)
    flash_attn<<<dim3(SEQ / 128, BATCH * NH), blk, FLASH_SMEM>>>(
        Qh, Ql, Kh, Kl, Vth, Vtl, CTX);

    // output projection
    cvt_hilo<<<(ROWS * HIDDEN / 4 + 255) / 256, blk>>>(CTX, Ch, Cl, ROWS * HIDDEN / 4);
    mma_nt<<<gproj, blk, SMEM_BYTES>>>(Ch, Cl, HIDDEN, 0, 0,
                                       Woh, Wol, HIDDEN, 0, 0,
                                       out, HIDDEN, 0, 0, HIDDEN, 1.0f);
}

// round 9
// speedup vs baseline: 6.1783x; 2.1541x over previous
#include <cuda_runtime.h>
#include <cuda_fp16.h>
#include <cstdint>
#include <math.h>

#define HIDDEN 2048
#define NH 16
#define HD 128
#define BATCH 2
#define SEQ 2048
#define ROWS (BATCH*SEQ)   /* 4096 */

// ---------------------------------------------------------------------------
// Scratch (allocation-free: __device__ globals)
// ---------------------------------------------------------------------------
__device__ float g_Q[ROWS * HIDDEN];
__device__ float g_K[ROWS * HIDDEN];
__device__ float g_V[ROWS * HIDDEN];
__device__ float g_ctx[ROWS * HIDDEN];

__device__ __half g_Xf[ROWS * HIDDEN];
__device__ __half g_Wqf[HIDDEN*HIDDEN];
__device__ __half g_Wkf[HIDDEN*HIDDEN];
__device__ __half g_Wvf[HIDDEN*HIDDEN];
__device__ __half g_Wof[HIDDEN*HIDDEN];
__device__ __half g_Qf[ROWS * HIDDEN];
__device__ __half g_Kf[ROWS * HIDDEN];
__device__ __half g_Vt[ROWS * HIDDEN];      /* V^T per head */
__device__ __half g_Cf[ROWS * HIDDEN];

// ---------------------------------------------------------------------------
__device__ __forceinline__ uint32_t smem_u32(const void* p) {
    uint32_t a;
    asm("{ .reg .u64 t; cvta.to.shared.u64 t, %1; cvt.u32.u64 %0, t; }"
        : "=r"(a) : "l"(p));
    return a;
}

__device__ __forceinline__ void cp_async16(uint32_t s, const void* g) {
    asm volatile("cp.async.cg.shared.global [%0], [%1], 16;\n"
                 :: "r"(s), "l"(g) : "memory");
}
#define CP_COMMIT()  asm volatile("cp.async.commit_group;\n" ::: "memory")
#define CP_WAIT_1()  asm volatile("cp.async.wait_group 1;\n" ::: "memory")
#define CP_WAIT_0()  asm volatile("cp.async.wait_group 0;\n" ::: "memory")

#define LDSM4(r, a) \
    asm volatile("ldmatrix.sync.aligned.m8n8.x4.shared.b16 {%0,%1,%2,%3}, [%4];" \
        : "=r"((r)[0]), "=r"((r)[1]), "=r"((r)[2]), "=r"((r)[3]) : "r"(a))

#define MMA_F16(c, a, b0, b1) \
    asm volatile("mma.sync.aligned.m16n8k16.row.col.f32.f16.f16.f32 " \
        "{%0,%1,%2,%3},{%4,%5,%6,%7},{%8,%9},{%0,%1,%2,%3};" \
        : "+f"((c)[0]), "+f"((c)[1]), "+f"((c)[2]), "+f"((c)[3]) \
        : "r"((a)[0]), "r"((a)[1]), "r"((a)[2]), "r"((a)[3]), "r"(b0), "r"(b1))

__device__ __forceinline__ uint32_t pack_h2(float x, float y) {
    __half2 t = __float22half2_rn(make_float2(x, y));
    return *(uint32_t*)&t;
}

// ---------------------------------------------------------------------------
// fp16 tensor-core GEMM:  C[M,N] = alpha * A[M,K] @ B[N,K]^T
// 128x128 CTA tile, BK=32, cp.async double buffer, 8 warps (64x32 warp tile).
// ---------------------------------------------------------------------------
#define SMS 40
#define TILE_E (128*SMS)          /* halves per tile */
#define BUF_E  (2*TILE_E)         /* A|B */
#define SMEM_BYTES (2*BUF_E*2)    /* 40960 */

__global__ __launch_bounds__(256) void mma_nt(
    const __half* __restrict__ A, int lda, long long saB, long long saH,
    const __half* __restrict__ B, int ldb, long long sbB, long long sbH,
    float* __restrict__ C, int ldc, long long scB, long long scH,
    int K, float alpha)
{
    extern __shared__ __half sm[];
    const uint32_t s0 = smem_u32(sm);
    const int tid = threadIdx.x;
    const int wid = tid >> 5, lane = tid & 31;

    const int z = blockIdx.z;
    const long long zb = z >> 4, zh = z & 15;
    A += zb * saB + zh * saH + (long long)blockIdx.y * 128 * lda;
    B += zb * sbB + zh * sbH + (long long)blockIdx.x * 128 * ldb;
    C += zb * scB + zh * scH + (long long)blockIdx.y * 128 * ldc
                             + (long long)blockIdx.x * 128;

    const int lrow = tid >> 1;           // 0..127
    const int lc0  = (tid & 1) * 2;      // chunks {0,1} or {2,3}

    const int wm = (wid >> 2) << 6;
    const int wn = (wid & 3) << 5;
    const int i8 = lane & 7, msel = lane >> 3;
    const int a_row = i8 + ((msel & 1) << 3);
    const int a_k   = (msel >> 1) << 3;
    const int b_row = i8 + ((msel >> 1) << 3);
    const int b_k   = (msel & 1) << 3;

    float acc[4][4][4];
    #pragma unroll
    for (int i = 0; i < 4; i++)
        #pragma unroll
        for (int j = 0; j < 4; j++)
            #pragma unroll
            for (int r = 0; r < 4; r++) acc[i][j][r] = 0.0f;

    const int NC = K >> 5;

    auto issue = [&](int c) {
        const int kt = c << 5;
        const uint32_t dbuf = s0 + (uint32_t)((c & 1) * BUF_E) * 2;
        const __half* ga = A + (long long)lrow * lda + kt;
        const __half* gb = B + (long long)lrow * ldb + kt;
        const uint32_t da = dbuf + (uint32_t)(lrow * SMS) * 2;
        const uint32_t db = da + TILE_E * 2;
        cp_async16(da + lc0 * 16,       ga + lc0 * 8);
        cp_async16(da + (lc0 + 1) * 16, ga + (lc0 + 1) * 8);
        cp_async16(db + lc0 * 16,       gb + lc0 * 8);
        cp_async16(db + (lc0 + 1) * 16, gb + (lc0 + 1) * 8);
        CP_COMMIT();
    };

    issue(0);

    for (int c = 0; c < NC; c++) {
        if (c + 1 < NC) { issue(c + 1); CP_WAIT_1(); }
        else            { CP_WAIT_0(); }
        __syncthreads();

        const uint32_t bA = s0 + (uint32_t)((c & 1) * BUF_E) * 2;
        const uint32_t bB = bA + TILE_E * 2;

        #pragma unroll
        for (int k16 = 0; k16 < 32; k16 += 16) {
            uint32_t af[4][4], bf[2][4];
            #pragma unroll
            for (int mi = 0; mi < 4; mi++)
                LDSM4(af[mi], bA + (uint32_t)(((wm + mi * 16 + a_row) * SMS)
                                              + k16 + a_k) * 2);
            #pragma unroll
            for (int ni = 0; ni < 2; ni++)
                LDSM4(bf[ni], bB + (uint32_t)(((wn + ni * 16 + b_row) * SMS)
                                              + k16 + b_k) * 2);
            #pragma unroll
            for (int mi = 0; mi < 4; mi++)
                #pragma unroll
                for (int nj = 0; nj < 4; nj++)
                    MMA_F16(acc[mi][nj], af[mi],
                            bf[nj >> 1][(nj & 1) * 2], bf[nj >> 1][(nj & 1) * 2 + 1]);
        }
        __syncthreads();
    }

    const int gr = lane >> 2, tc = (lane & 3) * 2;
    #pragma unroll
    for (int mi = 0; mi < 4; mi++) {
        const int row0 = wm + mi * 16 + gr;
        #pragma unroll
        for (int nj = 0; nj < 4; nj++) {
            const int col = wn + nj * 8 + tc;
            float2 lo, hi;
            lo.x = alpha * acc[mi][nj][0]; lo.y = alpha * acc[mi][nj][1];
            hi.x = alpha * acc[mi][nj][2]; hi.y = alpha * acc[mi][nj][3];
            *(float2*)(C + (long long)row0 * ldc + col)       = lo;
            *(float2*)(C + (long long)(row0 + 8) * ldc + col) = hi;
        }
    }
}

// ---------------------------------------------------------------------------
// Fused flash attention (fp16), double-buffered 64-key KV tiles, 2 CTAs/SM.
// CTA = (128 q-rows, one (b,h)); warp w owns q-rows [16w,16w+16).
// ---------------------------------------------------------------------------
#define FSTR 136                  /* Q/K tile row stride (halves) */
#define VSTR 72                   /* V tile row stride (halves)   */
#define QTILE_B (128*FSTR*2)      /* 34816 */
#define KTILE_B (64*FSTR*2)       /* 17408 */
#define VTILE_B (128*VSTR*2)      /* 18432 */
#define OFF_Q 0
#define OFF_K QTILE_B             /* 34816 */
#define OFF_V (OFF_K + 2*KTILE_B) /* 69632 */
#define FLASH_SMEM (OFF_V + 2*VTILE_B)   /* 106496 */

__global__ __launch_bounds__(256, 2) void flash_attn(
    const __half* __restrict__ Qf_, const __half* __restrict__ Kf_,
    const __half* __restrict__ Vt_, float* __restrict__ CTX)
{
    extern __shared__ __half sm[];
    const uint32_t s0 = smem_u32(sm);

    const int tid = threadIdx.x, wid = tid >> 5, lane = tid & 31;
    const int z = blockIdx.y, b = z >> 4, h = z & 15;
    const int q0 = blockIdx.x * 128;
    const long long SH = (long long)SEQ * HIDDEN;

    const __half* qf  = Qf_ + (long long)b * SH + h * HD + (long long)q0 * HIDDEN;
    const __half* kf0 = Kf_ + (long long)b * SH + h * HD;
    const __half* vt0 = Vt_ + (long long)z * HD * SEQ;

    // Q tile load (joins stage-0 commit group)
    {
        const int lrow = tid >> 1, lc0 = (tid & 1) * 8;
        const __half* g = qf + (long long)lrow * HIDDEN + lc0 * 8;
        const uint32_t d = s0 + OFF_Q + (uint32_t)(lrow * 272 + lc0 * 16);
        #pragma unroll
        for (int i = 0; i < 8; i++) cp_async16(d + i * 16, g + i * 8);
    }

    auto issueKV = [&](int kt) {
        const int st = kt & 1;
        const int kb = kt << 6;
        {   // K tile: 64 rows x 128 cols
            const int lrow = tid >> 2;
            const int lc   = (tid & 3) * 4;
            const __half* g = kf0 + (long long)(kb + lrow) * HIDDEN + lc * 8;
            const uint32_t d = s0 + OFF_K + (uint32_t)(st * KTILE_B
                               + lrow * 272 + lc * 16);
            #pragma unroll
            for (int i = 0; i < 4; i++) cp_async16(d + i * 16, g + i * 8);
        }
        {   // V tile: 128 rows (d) x 64 cols (s)
            const int lrow = tid >> 1;
            const int lc   = (tid & 1) * 4;
            const __half* g = vt0 + (long long)lrow * SEQ + kb + lc * 8;
            const uint32_t d = s0 + OFF_V + (uint32_t)(st * VTILE_B
                               + lrow * 144 + lc * 16);
            #pragma unroll
            for (int i = 0; i < 4; i++) cp_async16(d + i * 16, g + i * 8);
        }
        CP_COMMIT();
    };

    issueKV(0);

    const int i8 = lane & 7, msel = lane >> 3;
    const int a_row = i8 + ((msel & 1) << 3);
    const int a_k   = (msel >> 1) << 3;
    const int b_row = i8 + ((msel >> 1) << 3);
    const int b_k   = (msel & 1) << 3;
    const int wm = wid << 4;

    float o[16][4];
    #pragma unroll
    for (int t = 0; t < 16; t++)
        #pragma unroll
        for (int r = 0; r < 4; r++) o[t][r] = 0.0f;
    float m0 = -1e30f, m1 = -1e30f, l0 = 0.0f, l1 = 0.0f;

    const uint32_t bQ = s0 + OFF_Q;

    for (int kt = 0; kt < 32; kt++) {
        if (kt + 1 < 32) { issueKV(kt + 1); CP_WAIT_1(); }
        else             { CP_WAIT_0(); }
        __syncthreads();

        const uint32_t bK = s0 + OFF_K + (uint32_t)((kt & 1) * KTILE_B);
        const uint32_t bV = s0 + OFF_V + (uint32_t)((kt & 1) * VTILE_B);

        // ---- S = Q @ K^T (Q pre-scaled) : 16 q-rows x 64 k-cols ----
        float c[8][4];
        #pragma unroll
        for (int t = 0; t < 8; t++)
            #pragma unroll
            for (int r = 0; r < 4; r++) c[t][r] = 0.0f;

        #pragma unroll
        for (int k16 = 0; k16 < 128; k16 += 16) {
            uint32_t af[4];
            LDSM4(af, bQ + (uint32_t)(((wm + a_row) * FSTR) + k16 + a_k) * 2);
            #pragma unroll
            for (int g = 0; g < 4; g++) {
                uint32_t bfr[4];
                LDSM4(bfr, bK + (uint32_t)((((g << 4) + b_row) * FSTR) + k16 + b_k) * 2);
                MMA_F16(c[(g << 1) + 0], af, bfr[0], bfr[1]);
                MMA_F16(c[(g << 1) + 1], af, bfr[2], bfr[3]);
            }
        }

        // ---- online softmax ----
        float mx0 = c[0][0], mx1 = c[0][2];
        #pragma unroll
        for (int t = 0; t < 8; t++) {
            mx0 = fmaxf(mx0, fmaxf(c[t][0], c[t][1]));
            mx1 = fmaxf(mx1, fmaxf(c[t][2], c[t][3]));
        }
        mx0 = fmaxf(mx0, __shfl_xor_sync(0xFFFFFFFFu, mx0, 1));
        mx0 = fmaxf(mx0, __shfl_xor_sync(0xFFFFFFFFu, mx0, 2));
        mx1 = fmaxf(mx1, __shfl_xor_sync(0xFFFFFFFFu, mx1, 1));
        mx1 = fmaxf(mx1, __shfl_xor_sync(0xFFFFFFFFu, mx1, 2));
        const float nm0 = fmaxf(m0, mx0), nm1 = fmaxf(m1, mx1);
        const float al0 = __expf(m0 - nm0), al1 = __expf(m1 - nm1);
        m0 = nm0; m1 = nm1;

        float s0s = 0.0f, s1s = 0.0f;
        #pragma unroll
        for (int t = 0; t < 8; t++) {
            c[t][0] = __expf(c[t][0] - m0);
            c[t][1] = __expf(c[t][1] - m0);
            c[t][2] = __expf(c[t][2] - m1);
            c[t][3] = __expf(c[t][3] - m1);
            s0s += c[t][0] + c[t][1];
            s1s += c[t][2] + c[t][3];
        }
        s0s += __shfl_xor_sync(0xFFFFFFFFu, s0s, 1);
        s0s += __shfl_xor_sync(0xFFFFFFFFu, s0s, 2);
        s1s += __shfl_xor_sync(0xFFFFFFFFu, s1s, 1);
        s1s += __shfl_xor_sync(0xFFFFFFFFu, s1s, 2);
        l0 = l0 * al0 + s0s;
        l1 = l1 * al1 + s1s;

        #pragma unroll
        for (int t = 0; t < 16; t++) {
            o[t][0] *= al0; o[t][1] *= al0;
            o[t][2] *= al1; o[t][3] *= al1;
        }

        // ---- O += P @ V (P frags packed from registers) ----
        #pragma unroll
        for (int j = 0; j < 4; j++) {
            uint32_t ph[4];
            ph[0] = pack_h2(c[2*j][0],   c[2*j][1]);
            ph[1] = pack_h2(c[2*j][2],   c[2*j][3]);
            ph[2] = pack_h2(c[2*j+1][0], c[2*j+1][1]);
            ph[3] = pack_h2(c[2*j+1][2], c[2*j+1][3]);
            #pragma unroll
            for (int g = 0; g < 8; g++) {
                uint32_t vf[4];
                LDSM4(vf, bV + (uint32_t)((((g << 4) + b_row) * VSTR) + (j << 4) + b_k) * 2);
                MMA_F16(o[(g << 1) + 0], ph, vf[0], vf[1]);
                MMA_F16(o[(g << 1) + 1], ph, vf[2], vf[3]);
            }
        }
        __syncthreads();
    }

    // ---- epilogue ----
    const float i0 = 1.0f / l0, i1 = 1.0f / l1;
    const int r0 = q0 + wm + (lane >> 2);
    const int tc = (lane & 3) * 2;
    float* c0p = CTX + (long long)(b * SEQ + r0) * HIDDEN + h * HD;
    float* c1p = c0p + 8 * HIDDEN;
    #pragma unroll
    for (int t = 0; t < 16; t++) {
        const int col = t * 8 + tc;
        *(float2*)(c0p + col) = make_float2(o[t][0] * i0, o[t][1] * i0);
        *(float2*)(c1p + col) = make_float2(o[t][2] * i1, o[t][3] * i1);
    }
}

// ---------------------------------------------------------------------------
// fp32 -> fp16 convert
// ---------------------------------------------------------------------------
__global__ __launch_bounds__(256) void cvt_f16(const float* __restrict__ src,
                                               __half* __restrict__ dst, int n4)
{
    int i = blockIdx.x * 256 + threadIdx.x;
    if (i >= n4) return;
    float4 x = *(const float4*)(src + i * 4);
    __half2 a = __float22half2_rn(make_float2(x.x, x.y));
    __half2 b = __float22half2_rn(make_float2(x.z, x.w));
    *(__half2*)(dst + i * 4)     = a;
    *(__half2*)(dst + i * 4 + 2) = b;
}

// ---------------------------------------------------------------------------
// RoPE on Q,K (f32 in) -> fp16 out; Q pre-scaled by 1/sqrt(HD).
// ---------------------------------------------------------------------------
__global__ __launch_bounds__(256) void rope_cvt(
    const float* __restrict__ Q, const float* __restrict__ K,
    __half* __restrict__ Qf, __half* __restrict__ Kf)
{
    int idx = blockIdx.x * 256 + threadIdx.x;
    int j   = idx & 63;
    int h   = (idx >> 6) & (NH - 1);
    int row = idx >> 10;
    int s   = row & (SEQ - 1);

    const float scale = 0.08838834764831845f;   /* 1/sqrt(128) */
    float invf = powf(10000.0f, -(float)j * (1.0f / 64.0f));
    float ang  = (float)s * invf;
    float c = cosf(ang), sn = sinf(ang);

    long long base = (long long)row * HIDDEN + h * HD + j;
    float q0 = Q[base], q1 = Q[base + 64];
    float k0 = K[base], k1 = K[base + 64];
    Qf[base]      = __float2half((q0 * c - q1 * sn) * scale);
    Qf[base + 64] = __float2half((q1 * c + q0 * sn) * scale);
    Kf[base]      = __float2half(k0 * c - k1 * sn);
    Kf[base + 64] = __float2half(k1 * c + k0 * sn);
}

// ---------------------------------------------------------------------------
// Per-head transpose-convert of V: Vt[(z*128+d)*SEQ + s] = V[(b*SEQ+s)*H + h*128+d]
// ---------------------------------------------------------------------------
__global__ __launch_bounds__(256) void vtrans(const float* __restrict__ V,
                                              __half* __restrict__ Vt)
{
    __shared__ float t[32][33];
    int tx = threadIdx.x & 31, ty = threadIdx.x >> 5;
    int z = blockIdx.z, b = z >> 4, h = z & 15;
    int s0 = blockIdx.x * 32, d0 = blockIdx.y * 32;

    #pragma unroll
    for (int r = 0; r < 4; r++) {
        int s = s0 + ty + r * 8, d = d0 + tx;
        t[ty + r * 8][tx] = V[(long long)(b * SEQ + s) * HIDDEN + h * HD + d];
    }
    __syncthreads();
    #pragma unroll
    for (int r = 0; r < 4; r++) {
        int d = d0 + ty + r * 8, s = s0 + tx;
        Vt[(long long)(z * HD + d) * SEQ + s] = __float2half(t[tx][ty + r * 8]);
    }
}

// ---------------------------------------------------------------------------
extern "C" void kernel_launch(void* const* d_in, const int* in_sizes, int n_in,
                              void* d_out, int out_size)
{
    const float* X  = (const float*)d_in[0];
    const float* Wq = (const float*)d_in[1];
    const float* Wk = (const float*)d_in[2];
    const float* Wv = (const float*)d_in[3];
    const float* Wo = (const float*)d_in[4];
    float* out = (float*)d_out;

    float *Q, *K, *V, *CTX;
    __half *Xf, *Wqf, *Wkf, *Wvf, *Wof, *Qf, *Kf, *Vt, *Cf;
    cudaGetSymbolAddress((void**)&Q,   g_Q);
    cudaGetSymbolAddress((void**)&K,   g_K);
    cudaGetSymbolAddress((void**)&V,   g_V);
    cudaGetSymbolAddress((void**)&CTX, g_ctx);
    cudaGetSymbolAddress((void**)&Xf,  g_Xf);
    cudaGetSymbolAddress((void**)&Wqf, g_Wqf);
    cudaGetSymbolAddress((void**)&Wkf, g_Wkf);
    cudaGetSymbolAddress((void**)&Wvf, g_Wvf);
    cudaGetSymbolAddress((void**)&Wof, g_Wof);
    cudaGetSymbolAddress((void**)&Qf,  g_Qf);
    cudaGetSymbolAddress((void**)&Kf,  g_Kf);
    cudaGetSymbolAddress((void**)&Vt,  g_Vt);
    cudaGetSymbolAddress((void**)&Cf,  g_Cf);

    cudaFuncSetAttribute(mma_nt, cudaFuncAttributeMaxDynamicSharedMemorySize,
                         SMEM_BYTES);
    cudaFuncSetAttribute(flash_attn, cudaFuncAttributeMaxDynamicSharedMemorySize,
                         FLASH_SMEM);

    dim3 blk(256);

    // Convert inputs to fp16
    cvt_f16<<<(ROWS * HIDDEN / 4 + 255) / 256, blk>>>(X,  Xf,  ROWS * HIDDEN / 4);
    cvt_f16<<<(HIDDEN * HIDDEN / 4 + 255) / 256, blk>>>(Wq, Wqf, HIDDEN * HIDDEN / 4);
    cvt_f16<<<(HIDDEN * HIDDEN / 4 + 255) / 256, blk>>>(Wk, Wkf, HIDDEN * HIDDEN / 4);
    cvt_f16<<<(HIDDEN * HIDDEN / 4 + 255) / 256, blk>>>(Wv, Wvf, HIDDEN * HIDDEN / 4);
    cvt_f16<<<(HIDDEN * HIDDEN / 4 + 255) / 256, blk>>>(Wo, Wof, HIDDEN * HIDDEN / 4);

    // QKV projections -> f32
    dim3 gproj(HIDDEN / 128, ROWS / 128, 1);
    mma_nt<<<gproj, blk, SMEM_BYTES>>>(Xf, HIDDEN, 0, 0, Wqf, HIDDEN, 0, 0,
                                       Q, HIDDEN, 0, 0, HIDDEN, 1.0f);
    mma_nt<<<gproj, blk, SMEM_BYTES>>>(Xf, HIDDEN, 0, 0, Wkf, HIDDEN, 0, 0,
                                       K, HIDDEN, 0, 0, HIDDEN, 1.0f);
    mma_nt<<<gproj, blk, SMEM_BYTES>>>(Xf, HIDDEN, 0, 0, Wvf, HIDDEN, 0, 0,
                                       V, HIDDEN, 0, 0, HIDDEN, 1.0f);

    // RoPE + convert Q,K (Q pre-scaled) ; transpose-convert V
    rope_cvt<<<(ROWS * NH * 64) / 256, blk>>>(Q, K, Qf, Kf);
    vtrans<<<dim3(SEQ / 32, HD / 32, BATCH * NH), blk>>>(V, Vt);

    // Fused attention
    flash_attn<<<dim3(SEQ / 128, BATCH * NH), blk, FLASH_SMEM>>>(Qf, Kf, Vt, CTX);

    // output projection
    cvt_f16<<<(ROWS * HIDDEN / 4 + 255) / 256, blk>>>(CTX, Cf, ROWS * HIDDEN / 4);
    mma_nt<<<gproj, blk, SMEM_BYTES>>>(Cf, HIDDEN, 0, 0, Wof, HIDDEN, 0, 0,
                                       out, HIDDEN, 0, 0, HIDDEN, 1.0f);
}

// round 10
// speedup vs baseline: 6.4746x; 1.0480x over previous
#include <cuda_runtime.h>
#include <cuda_fp16.h>
#include <cstdint>
#include <math.h>

#define HIDDEN 2048
#define NH 16
#define HD 128
#define BATCH 2
#define SEQ 2048
#define ROWS (BATCH*SEQ)   /* 4096 */

// ---------------------------------------------------------------------------
// Scratch (allocation-free: __device__ globals) — all fp16 now
// ---------------------------------------------------------------------------
__device__ __half g_Xf[ROWS * HIDDEN];
__device__ __half g_Wqf[HIDDEN*HIDDEN];
__device__ __half g_Wkf[HIDDEN*HIDDEN];
__device__ __half g_Wvf[HIDDEN*HIDDEN];
__device__ __half g_Wof[HIDDEN*HIDDEN];
__device__ __half g_Qf[ROWS * HIDDEN];
__device__ __half g_Kf[ROWS * HIDDEN];
__device__ __half g_Vt[ROWS * HIDDEN];      /* V^T per head */
__device__ __half g_Cf[ROWS * HIDDEN];      /* attention output (fp16) */

// ---------------------------------------------------------------------------
__device__ __forceinline__ uint32_t smem_u32(const void* p) {
    uint32_t a;
    asm("{ .reg .u64 t; cvta.to.shared.u64 t, %1; cvt.u32.u64 %0, t; }"
        : "=r"(a) : "l"(p));
    return a;
}

__device__ __forceinline__ void cp_async16(uint32_t s, const void* g) {
    asm volatile("cp.async.cg.shared.global [%0], [%1], 16;\n"
                 :: "r"(s), "l"(g) : "memory");
}
#define CP_COMMIT()  asm volatile("cp.async.commit_group;\n" ::: "memory")
#define CP_WAIT_1()  asm volatile("cp.async.wait_group 1;\n" ::: "memory")
#define CP_WAIT_0()  asm volatile("cp.async.wait_group 0;\n" ::: "memory")

#define LDSM4(r, a) \
    asm volatile("ldmatrix.sync.aligned.m8n8.x4.shared.b16 {%0,%1,%2,%3}, [%4];" \
        : "=r"((r)[0]), "=r"((r)[1]), "=r"((r)[2]), "=r"((r)[3]) : "r"(a))

#define MMA_F16(c, a, b0, b1) \
    asm volatile("mma.sync.aligned.m16n8k16.row.col.f32.f16.f16.f32 " \
        "{%0,%1,%2,%3},{%4,%5,%6,%7},{%8,%9},{%0,%1,%2,%3};" \
        : "+f"((c)[0]), "+f"((c)[1]), "+f"((c)[2]), "+f"((c)[3]) \
        : "r"((a)[0]), "r"((a)[1]), "r"((a)[2]), "r"((a)[3]), "r"(b0), "r"(b1))

__device__ __forceinline__ uint32_t pack_h2(float x, float y) {
    __half2 t = __float22half2_rn(make_float2(x, y));
    return *(uint32_t*)&t;
}

// ---------------------------------------------------------------------------
// Shared GEMM mainloop config (128x128 CTA tile, BK=32, 8 warps)
// ---------------------------------------------------------------------------
#define SMS 40
#define TILE_E (128*SMS)          /* halves per tile */
#define BUF_E  (2*TILE_E)         /* A|B */
#define GEMM_SMEM (2*BUF_E*2)     /* 40960 */
#define STAGE_STRIDE 133
#define QKV_SMEM (128*STAGE_STRIDE*4)   /* 68096 f32 staging (>= GEMM_SMEM) */

// mainloop macro body shared by both GEMM kernels -----------------------------
#define GEMM_MAINLOOP(Aptr, Bptr, NC)                                          \
    const int lrow = tid >> 1;                                                 \
    const int lc0  = (tid & 1) * 2;                                            \
    const int wm = (wid >> 2) << 6;                                            \
    const int wn = (wid & 3) << 5;                                             \
    const int i8 = lane & 7, msel = lane >> 3;                                 \
    const int a_row = i8 + ((msel & 1) << 3);                                  \
    const int a_k   = (msel >> 1) << 3;                                        \
    const int b_row = i8 + ((msel >> 1) << 3);                                 \
    const int b_k   = (msel & 1) << 3;                                         \
    float acc[4][4][4];                                                        \
    _Pragma("unroll")                                                          \
    for (int i = 0; i < 4; i++)                                                \
        _Pragma("unroll")                                                      \
        for (int j = 0; j < 4; j++)                                            \
            _Pragma("unroll")                                                  \
            for (int r = 0; r < 4; r++) acc[i][j][r] = 0.0f;                   \
    auto issue = [&](int c) {                                                  \
        const int kt = c << 5;                                                 \
        const uint32_t dbuf = s0 + (uint32_t)((c & 1) * BUF_E) * 2;            \
        const __half* ga = (Aptr) + (long long)lrow * HIDDEN + kt;             \
        const __half* gb = (Bptr) + (long long)lrow * HIDDEN + kt;             \
        const uint32_t da = dbuf + (uint32_t)(lrow * SMS) * 2;                 \
        const uint32_t db = da + TILE_E * 2;                                   \
        cp_async16(da + lc0 * 16,       ga + lc0 * 8);                         \
        cp_async16(da + (lc0 + 1) * 16, ga + (lc0 + 1) * 8);                   \
        cp_async16(db + lc0 * 16,       gb + lc0 * 8);                         \
        cp_async16(db + (lc0 + 1) * 16, gb + (lc0 + 1) * 8);                   \
        CP_COMMIT();                                                           \
    };                                                                         \
    issue(0);                                                                  \
    for (int c = 0; c < (NC); c++) {                                           \
        if (c + 1 < (NC)) { issue(c + 1); CP_WAIT_1(); }                       \
        else              { CP_WAIT_0(); }                                     \
        __syncthreads();                                                       \
        const uint32_t bA = s0 + (uint32_t)((c & 1) * BUF_E) * 2;              \
        const uint32_t bB = bA + TILE_E * 2;                                   \
        _Pragma("unroll")                                                      \
        for (int k16 = 0; k16 < 32; k16 += 16) {                               \
            uint32_t af[4][4], bf[2][4];                                       \
            _Pragma("unroll")                                                  \
            for (int mi = 0; mi < 4; mi++)                                     \
                LDSM4(af[mi], bA + (uint32_t)(((wm + mi * 16 + a_row) * SMS)   \
                                              + k16 + a_k) * 2);               \
            _Pragma("unroll")                                                  \
            for (int ni = 0; ni < 2; ni++)                                     \
                LDSM4(bf[ni], bB + (uint32_t)(((wn + ni * 16 + b_row) * SMS)   \
                                              + k16 + b_k) * 2);               \
            _Pragma("unroll")                                                  \
            for (int mi = 0; mi < 4; mi++)                                     \
                _Pragma("unroll")                                              \
                for (int nj = 0; nj < 4; nj++)                                 \
                    MMA_F16(acc[mi][nj], af[mi],                               \
                            bf[nj >> 1][(nj & 1) * 2],                         \
                            bf[nj >> 1][(nj & 1) * 2 + 1]);                    \
        }                                                                      \
        __syncthreads();                                                       \
    }

// ---------------------------------------------------------------------------
// Fused QKV projection: grid (16, 32, 3); z=0:Q(rope+scale), 1:K(rope),
// 2:V(transpose). Epilogue stages acc in smem f32, emits fp16 directly.
// ---------------------------------------------------------------------------
__global__ __launch_bounds__(256) void mma_qkv(
    const __half* __restrict__ Xf,
    const __half* __restrict__ Wq, const __half* __restrict__ Wk,
    const __half* __restrict__ Wv,
    __half* __restrict__ Qf, __half* __restrict__ Kf, __half* __restrict__ Vt)
{
    extern __shared__ __half sm[];
    const uint32_t s0 = smem_u32(sm);
    const int tid = threadIdx.x;
    const int wid = tid >> 5, lane = tid & 31;
    const int zp = blockIdx.z;

    const __half* A = Xf + (long long)blockIdx.y * 128 * HIDDEN;
    const __half* W = (zp == 0) ? Wq : (zp == 1) ? Wk : Wv;
    const __half* B = W + (long long)blockIdx.x * 128 * HIDDEN;

    GEMM_MAINLOOP(A, B, HIDDEN >> 5)

    // ---- stage accumulators to smem (f32, stride 133) ----
    float* fsm = reinterpret_cast<float*>(sm);
    const int gr = lane >> 2, tcc = (lane & 3) * 2;
    #pragma unroll
    for (int mi = 0; mi < 4; mi++) {
        const int r0 = wm + mi * 16 + gr;
        #pragma unroll
        for (int nj = 0; nj < 4; nj++) {
            const int col = wn + nj * 8 + tcc;
            fsm[r0 * STAGE_STRIDE + col]           = acc[mi][nj][0];
            fsm[r0 * STAGE_STRIDE + col + 1]       = acc[mi][nj][1];
            fsm[(r0 + 8) * STAGE_STRIDE + col]     = acc[mi][nj][2];
            fsm[(r0 + 8) * STAGE_STRIDE + col + 1] = acc[mi][nj][3];
        }
    }
    __syncthreads();

    if (zp < 2) {
        // ---- RoPE epilogue (Q: scaled, K: unscaled) ----
        const int r  = tid >> 1;
        const int j0 = (tid & 1) * 32;
        const long long gy = (long long)blockIdx.y * 128 + r;
        const int s = (int)(gy & (SEQ - 1));
        const float qsc = (zp == 0) ? 0.08838834764831845f : 1.0f;
        __half* dst = ((zp == 0) ? Qf : Kf) + gy * HIDDEN + blockIdx.x * 128;
        #pragma unroll 4
        for (int j = j0; j < j0 + 32; j += 2) {
            float v0a = fsm[r * STAGE_STRIDE + j];
            float v1a = fsm[r * STAGE_STRIDE + j + 64];
            float v0b = fsm[r * STAGE_STRIDE + j + 1];
            float v1b = fsm[r * STAGE_STRIDE + j + 65];
            float anga = (float)s * exp2f((float)j       * -0.20762050593046f);
            float angb = (float)s * exp2f((float)(j + 1) * -0.20762050593046f);
            float ca, sa, cb, sb2;
            sincosf(anga, &sa, &ca);
            sincosf(angb, &sb2, &cb);
            float o0a = (v0a * ca - v1a * sa) * qsc;
            float o1a = (v1a * ca + v0a * sa) * qsc;
            float o0b = (v0b * cb - v1b * sb2) * qsc;
            float o1b = (v1b * cb + v0b * sb2) * qsc;
            *(__half2*)(dst + j)      = __float22half2_rn(make_float2(o0a, o0b));
            *(__half2*)(dst + j + 64) = __float22half2_rn(make_float2(o1a, o1b));
        }
    } else {
        // ---- V transpose epilogue: Vt[((b*16+h)*128+d)*SEQ + s] ----
        const int d   = tid >> 1;
        const int si0 = (tid & 1) * 64;
        const int b   = (blockIdx.y * 128) >> 11;
        const int sbase = (blockIdx.y * 128) & (SEQ - 1);
        __half* dst = Vt + ((long long)((b * NH + blockIdx.x) * HD + d)) * SEQ
                         + sbase + si0;
        #pragma unroll 8
        for (int sl = 0; sl < 64; sl += 2) {
            float v0 = fsm[(si0 + sl) * STAGE_STRIDE + d];
            float v1 = fsm[(si0 + sl + 1) * STAGE_STRIDE + d];
            *(__half2*)(dst + sl) = __float22half2_rn(make_float2(v0, v1));
        }
    }
}

// ---------------------------------------------------------------------------
// Output projection: out[M,N] = Cf[M,K] @ Wo[N,K]^T  (f32 output)
// ---------------------------------------------------------------------------
__global__ __launch_bounds__(256) void mma_out(
    const __half* __restrict__ Cf, const __half* __restrict__ Wo,
    float* __restrict__ C)
{
    extern __shared__ __half sm[];
    const uint32_t s0 = smem_u32(sm);
    const int tid = threadIdx.x;
    const int wid = tid >> 5, lane = tid & 31;

    const __half* A = Cf + (long long)blockIdx.y * 128 * HIDDEN;
    const __half* B = Wo + (long long)blockIdx.x * 128 * HIDDEN;
    C += (long long)blockIdx.y * 128 * HIDDEN + (long long)blockIdx.x * 128;

    GEMM_MAINLOOP(A, B, HIDDEN >> 5)

    const int gr = lane >> 2, tcc = (lane & 3) * 2;
    #pragma unroll
    for (int mi = 0; mi < 4; mi++) {
        const int row0 = wm + mi * 16 + gr;
        #pragma unroll
        for (int nj = 0; nj < 4; nj++) {
            const int col = wn + nj * 8 + tcc;
            *(float2*)(C + (long long)row0 * HIDDEN + col) =
                make_float2(acc[mi][nj][0], acc[mi][nj][1]);
            *(float2*)(C + (long long)(row0 + 8) * HIDDEN + col) =
                make_float2(acc[mi][nj][2], acc[mi][nj][3]);
        }
    }
}

// ---------------------------------------------------------------------------
// Fused flash attention (fp16), double-buffered 64-key KV tiles, 2 CTAs/SM.
// Writes fp16 ctx directly.
// ---------------------------------------------------------------------------
#define FSTR 136
#define VSTR 72
#define QTILE_B (128*FSTR*2)
#define KTILE_B (64*FSTR*2)
#define VTILE_B (128*VSTR*2)
#define OFF_Q 0
#define OFF_K QTILE_B
#define OFF_V (OFF_K + 2*KTILE_B)
#define FLASH_SMEM (OFF_V + 2*VTILE_B)   /* 106496 */

__global__ __launch_bounds__(256, 2) void flash_attn(
    const __half* __restrict__ Qf_, const __half* __restrict__ Kf_,
    const __half* __restrict__ Vt_, __half* __restrict__ Cf)
{
    extern __shared__ __half sm[];
    const uint32_t s0 = smem_u32(sm);

    const int tid = threadIdx.x, wid = tid >> 5, lane = tid & 31;
    const int z = blockIdx.y, b = z >> 4, h = z & 15;
    const int q0 = blockIdx.x * 128;
    const long long SH = (long long)SEQ * HIDDEN;

    const __half* qf  = Qf_ + (long long)b * SH + h * HD + (long long)q0 * HIDDEN;
    const __half* kf0 = Kf_ + (long long)b * SH + h * HD;
    const __half* vt0 = Vt_ + (long long)z * HD * SEQ;

    {
        const int lrow = tid >> 1, lc0 = (tid & 1) * 8;
        const __half* g = qf + (long long)lrow * HIDDEN + lc0 * 8;
        const uint32_t d = s0 + OFF_Q + (uint32_t)(lrow * 272 + lc0 * 16);
        #pragma unroll
        for (int i = 0; i < 8; i++) cp_async16(d + i * 16, g + i * 8);
    }

    auto issueKV = [&](int kt) {
        const int st = kt & 1;
        const int kb = kt << 6;
        {
            const int lrow = tid >> 2;
            const int lc   = (tid & 3) * 4;
            const __half* g = kf0 + (long long)(kb + lrow) * HIDDEN + lc * 8;
            const uint32_t d = s0 + OFF_K + (uint32_t)(st * KTILE_B
                               + lrow * 272 + lc * 16);
            #pragma unroll
            for (int i = 0; i < 4; i++) cp_async16(d + i * 16, g + i * 8);
        }
        {
            const int lrow = tid >> 1;
            const int lc   = (tid & 1) * 4;
            const __half* g = vt0 + (long long)lrow * SEQ + kb + lc * 8;
            const uint32_t d = s0 + OFF_V + (uint32_t)(st * VTILE_B
                               + lrow * 144 + lc * 16);
            #pragma unroll
            for (int i = 0; i < 4; i++) cp_async16(d + i * 16, g + i * 8);
        }
        CP_COMMIT();
    };

    issueKV(0);

    const int i8 = lane & 7, msel = lane >> 3;
    const int a_row = i8 + ((msel & 1) << 3);
    const int a_k   = (msel >> 1) << 3;
    const int b_row = i8 + ((msel >> 1) << 3);
    const int b_k   = (msel & 1) << 3;
    const int wm = wid << 4;

    float o[16][4];
    #pragma unroll
    for (int t = 0; t < 16; t++)
        #pragma unroll
        for (int r = 0; r < 4; r++) o[t][r] = 0.0f;
    float m0 = -1e30f, m1 = -1e30f, l0 = 0.0f, l1 = 0.0f;

    const uint32_t bQ = s0 + OFF_Q;

    for (int kt = 0; kt < 32; kt++) {
        if (kt + 1 < 32) { issueKV(kt + 1); CP_WAIT_1(); }
        else             { CP_WAIT_0(); }
        __syncthreads();

        const uint32_t bK = s0 + OFF_K + (uint32_t)((kt & 1) * KTILE_B);
        const uint32_t bV = s0 + OFF_V + (uint32_t)((kt & 1) * VTILE_B);

        float c[8][4];
        #pragma unroll
        for (int t = 0; t < 8; t++)
            #pragma unroll
            for (int r = 0; r < 4; r++) c[t][r] = 0.0f;

        #pragma unroll
        for (int k16 = 0; k16 < 128; k16 += 16) {
            uint32_t af[4];
            LDSM4(af, bQ + (uint32_t)(((wm + a_row) * FSTR) + k16 + a_k) * 2);
            #pragma unroll
            for (int g = 0; g < 4; g++) {
                uint32_t bfr[4];
                LDSM4(bfr, bK + (uint32_t)((((g << 4) + b_row) * FSTR) + k16 + b_k) * 2);
                MMA_F16(c[(g << 1) + 0], af, bfr[0], bfr[1]);
                MMA_F16(c[(g << 1) + 1], af, bfr[2], bfr[3]);
            }
        }

        float mx0 = c[0][0], mx1 = c[0][2];
        #pragma unroll
        for (int t = 0; t < 8; t++) {
            mx0 = fmaxf(mx0, fmaxf(c[t][0], c[t][1]));
            mx1 = fmaxf(mx1, fmaxf(c[t][2], c[t][3]));
        }
        mx0 = fmaxf(mx0, __shfl_xor_sync(0xFFFFFFFFu, mx0, 1));
        mx0 = fmaxf(mx0, __shfl_xor_sync(0xFFFFFFFFu, mx0, 2));
        mx1 = fmaxf(mx1, __shfl_xor_sync(0xFFFFFFFFu, mx1, 1));
        mx1 = fmaxf(mx1, __shfl_xor_sync(0xFFFFFFFFu, mx1, 2));
        const float nm0 = fmaxf(m0, mx0), nm1 = fmaxf(m1, mx1);
        const float al0 = __expf(m0 - nm0), al1 = __expf(m1 - nm1);
        m0 = nm0; m1 = nm1;

        float s0s = 0.0f, s1s = 0.0f;
        #pragma unroll
        for (int t = 0; t < 8; t++) {
            c[t][0] = __expf(c[t][0] - m0);
            c[t][1] = __expf(c[t][1] - m0);
            c[t][2] = __expf(c[t][2] - m1);
            c[t][3] = __expf(c[t][3] - m1);
            s0s += c[t][0] + c[t][1];
            s1s += c[t][2] + c[t][3];
        }
        s0s += __shfl_xor_sync(0xFFFFFFFFu, s0s, 1);
        s0s += __shfl_xor_sync(0xFFFFFFFFu, s0s, 2);
        s1s += __shfl_xor_sync(0xFFFFFFFFu, s1s, 1);
        s1s += __shfl_xor_sync(0xFFFFFFFFu, s1s, 2);
        l0 = l0 * al0 + s0s;
        l1 = l1 * al1 + s1s;

        #pragma unroll
        for (int t = 0; t < 16; t++) {
            o[t][0] *= al0; o[t][1] *= al0;
            o[t][2] *= al1; o[t][3] *= al1;
        }

        #pragma unroll
        for (int j = 0; j < 4; j++) {
            uint32_t ph[4];
            ph[0] = pack_h2(c[2*j][0],   c[2*j][1]);
            ph[1] = pack_h2(c[2*j][2],   c[2*j][3]);
            ph[2] = pack_h2(c[2*j+1][0], c[2*j+1][1]);
            ph[3] = pack_h2(c[2*j+1][2], c[2*j+1][3]);
            #pragma unroll
            for (int g = 0; g < 8; g++) {
                uint32_t vf[4];
                LDSM4(vf, bV + (uint32_t)((((g << 4) + b_row) * VSTR) + (j << 4) + b_k) * 2);
                MMA_F16(o[(g << 1) + 0], ph, vf[0], vf[1]);
                MMA_F16(o[(g << 1) + 1], ph, vf[2], vf[3]);
            }
        }
        __syncthreads();
    }

    // ---- epilogue: O /= l, write fp16 ctx ----
    const float i0 = 1.0f / l0, i1 = 1.0f / l1;
    const int r0 = q0 + wm + (lane >> 2);
    const int tc = (lane & 3) * 2;
    __half* c0p = Cf + (long long)(b * SEQ + r0) * HIDDEN + h * HD;
    __half* c1p = c0p + 8 * HIDDEN;
    #pragma unroll
    for (int t = 0; t < 16; t++) {
        const int col = t * 8 + tc;
        *(__half2*)(c0p + col) = __float22half2_rn(make_float2(o[t][0] * i0, o[t][1] * i0));
        *(__half2*)(c1p + col) = __float22half2_rn(make_float2(o[t][2] * i1, o[t][3] * i1));
    }
}

// ---------------------------------------------------------------------------
// fp32 -> fp16 convert
// ---------------------------------------------------------------------------
__global__ __launch_bounds__(256) void cvt_f16(const float* __restrict__ src,
                                               __half* __restrict__ dst, int n4)
{
    int i = blockIdx.x * 256 + threadIdx.x;
    if (i >= n4) return;
    float4 x = *(const float4*)(src + i * 4);
    *(__half2*)(dst + i * 4)     = __float22half2_rn(make_float2(x.x, x.y));
    *(__half2*)(dst + i * 4 + 2) = __float22half2_rn(make_float2(x.z, x.w));
}

// ---------------------------------------------------------------------------
extern "C" void kernel_launch(void* const* d_in, const int* in_sizes, int n_in,
                              void* d_out, int out_size)
{
    const float* X  = (const float*)d_in[0];
    const float* Wq = (const float*)d_in[1];
    const float* Wk = (const float*)d_in[2];
    const float* Wv = (const float*)d_in[3];
    const float* Wo = (const float*)d_in[4];
    float* out = (float*)d_out;

    __half *Xf, *Wqf, *Wkf, *Wvf, *Wof, *Qf, *Kf, *Vt, *Cf;
    cudaGetSymbolAddress((void**)&Xf,  g_Xf);
    cudaGetSymbolAddress((void**)&Wqf, g_Wqf);
    cudaGetSymbolAddress((void**)&Wkf, g_Wkf);
    cudaGetSymbolAddress((void**)&Wvf, g_Wvf);
    cudaGetSymbolAddress((void**)&Wof, g_Wof);
    cudaGetSymbolAddress((void**)&Qf,  g_Qf);
    cudaGetSymbolAddress((void**)&Kf,  g_Kf);
    cudaGetSymbolAddress((void**)&Vt,  g_Vt);
    cudaGetSymbolAddress((void**)&Cf,  g_Cf);

    cudaFuncSetAttribute(mma_qkv, cudaFuncAttributeMaxDynamicSharedMemorySize,
                         QKV_SMEM);
    cudaFuncSetAttribute(mma_out, cudaFuncAttributeMaxDynamicSharedMemorySize,
                         GEMM_SMEM);
    cudaFuncSetAttribute(flash_attn, cudaFuncAttributeMaxDynamicSharedMemorySize,
                         FLASH_SMEM);

    dim3 blk(256);

    // Convert inputs to fp16
    cvt_f16<<<(ROWS * HIDDEN / 4 + 255) / 256, blk>>>(X,  Xf,  ROWS * HIDDEN / 4);
    cvt_f16<<<(HIDDEN * HIDDEN / 4 + 255) / 256, blk>>>(Wq, Wqf, HIDDEN * HIDDEN / 4);
    cvt_f16<<<(HIDDEN * HIDDEN / 4 + 255) / 256, blk>>>(Wk, Wkf, HIDDEN * HIDDEN / 4);
    cvt_f16<<<(HIDDEN * HIDDEN / 4 + 255) / 256, blk>>>(Wv, Wvf, HIDDEN * HIDDEN / 4);
    cvt_f16<<<(HIDDEN * HIDDEN / 4 + 255) / 256, blk>>>(Wo, Wof, HIDDEN * HIDDEN / 4);

    // Fused QKV projections + rope/scale/transpose epilogues -> fp16
    mma_qkv<<<dim3(HIDDEN / 128, ROWS / 128, 3), blk, QKV_SMEM>>>(
        Xf, Wqf, Wkf, Wvf, Qf, Kf, Vt);

    // Fused attention -> fp16 ctx
    flash_attn<<<dim3(SEQ / 128, BATCH * NH), blk, FLASH_SMEM>>>(Qf, Kf, Vt, Cf);

    // Output projection -> f32 out
    mma_out<<<dim3(HIDDEN / 128, ROWS / 128), blk, GEMM_SMEM>>>(Cf, Wof, out);
}

// round 11
// speedup vs baseline: 7.1441x; 1.1034x over previous
#include <cuda_runtime.h>
#include <cuda_fp16.h>
#include <cstdint>
#include <math.h>

#define HIDDEN 2048
#define NH 16
#define HD 128
#define BATCH 2
#define SEQ 2048
#define ROWS (BATCH*SEQ)   /* 4096 */

// ---------------------------------------------------------------------------
// Scratch (allocation-free: __device__ globals) — all fp16
// ---------------------------------------------------------------------------
__device__ __half g_Xf[ROWS * HIDDEN];
__device__ __half g_Wqf[HIDDEN*HIDDEN];
__device__ __half g_Wkf[HIDDEN*HIDDEN];
__device__ __half g_Wvf[HIDDEN*HIDDEN];
__device__ __half g_Wof[HIDDEN*HIDDEN];
__device__ __half g_Qf[ROWS * HIDDEN];
__device__ __half g_Kf[ROWS * HIDDEN];
__device__ __half g_Vt[ROWS * HIDDEN];      /* V^T per head */
__device__ __half g_Cf[ROWS * HIDDEN];      /* attention output (fp16) */

// ---------------------------------------------------------------------------
__device__ __forceinline__ uint32_t smem_u32(const void* p) {
    uint32_t a;
    asm("{ .reg .u64 t; cvta.to.shared.u64 t, %1; cvt.u32.u64 %0, t; }"
        : "=r"(a) : "l"(p));
    return a;
}

__device__ __forceinline__ void cp_async16(uint32_t s, const void* g) {
    asm volatile("cp.async.cg.shared.global [%0], [%1], 16;\n"
                 :: "r"(s), "l"(g) : "memory");
}
#define CP_COMMIT()  asm volatile("cp.async.commit_group;\n" ::: "memory")
#define CP_WAIT_1()  asm volatile("cp.async.wait_group 1;\n" ::: "memory")
#define CP_WAIT_0()  asm volatile("cp.async.wait_group 0;\n" ::: "memory")

#define LDSM4(r, a) \
    asm volatile("ldmatrix.sync.aligned.m8n8.x4.shared.b16 {%0,%1,%2,%3}, [%4];" \
        : "=r"((r)[0]), "=r"((r)[1]), "=r"((r)[2]), "=r"((r)[3]) : "r"(a))

#define MMA_F16(c, a, b0, b1) \
    asm volatile("mma.sync.aligned.m16n8k16.row.col.f32.f16.f16.f32 " \
        "{%0,%1,%2,%3},{%4,%5,%6,%7},{%8,%9},{%0,%1,%2,%3};" \
        : "+f"((c)[0]), "+f"((c)[1]), "+f"((c)[2]), "+f"((c)[3]) \
        : "r"((a)[0]), "r"((a)[1]), "r"((a)[2]), "r"((a)[3]), "r"(b0), "r"(b1))

__device__ __forceinline__ uint32_t pack_h2(float x, float y) {
    __half2 t = __float22half2_rn(make_float2(x, y));
    return *(uint32_t*)&t;
}

// ---------------------------------------------------------------------------
// Shared GEMM config (128x128 CTA tile, BK=32, 8 warps, 3-stage pipeline)
// ---------------------------------------------------------------------------
#define SMS 40
#define TILE_E (128*SMS)          /* halves per tile */
#define BUF_E  (2*TILE_E)         /* A|B per stage */
#define GEMM_SMEM (3*BUF_E*2)     /* 61440: 3 stages */
#define STAGE_STRIDE 133
#define QKV_SMEM (128*STAGE_STRIDE*4)   /* 68096 f32 staging (>= GEMM_SMEM) */

// 3-stage mainloop, ONE __syncthreads per chunk.
// Order per iter c: wait(group c done) -> barrier -> issue(c+2) -> compute(c).
// Safety: buffer (c+2)%3 == (c-1)%3 was last read in iter c-1; the barrier is
// passed only after ALL warps finished iter c-1's compute (they arrive at this
// barrier from iter c after their compute of c-1... barrier at iter c is
// reached only after each warp completed compute(c-1)), so the overwrite is safe.
#define GEMM_MAINLOOP(Aptr, Bptr, NC)                                          \
    const int lrow = tid >> 1;                                                 \
    const int lc0  = (tid & 1) * 2;                                            \
    const int wm = (wid >> 2) << 6;                                            \
    const int wn = (wid & 3) << 5;                                             \
    const int i8 = lane & 7, msel = lane >> 3;                                 \
    const int a_row = i8 + ((msel & 1) << 3);                                  \
    const int a_k   = (msel >> 1) << 3;                                        \
    const int b_row = i8 + ((msel >> 1) << 3);                                 \
    const int b_k   = (msel & 1) << 3;                                         \
    float acc[4][4][4];                                                        \
    _Pragma("unroll")                                                          \
    for (int i = 0; i < 4; i++)                                                \
        _Pragma("unroll")                                                      \
        for (int j = 0; j < 4; j++)                                            \
            _Pragma("unroll")                                                  \
            for (int r = 0; r < 4; r++) acc[i][j][r] = 0.0f;                   \
    auto issue = [&](int c) {                                                  \
        const int kt = c << 5;                                                 \
        const int st = c % 3;                                                  \
        const uint32_t dbuf = s0 + (uint32_t)(st * BUF_E) * 2;                 \
        const __half* ga = (Aptr) + (long long)lrow * HIDDEN + kt;             \
        const __half* gb = (Bptr) + (long long)lrow * HIDDEN + kt;             \
        const uint32_t da = dbuf + (uint32_t)(lrow * SMS) * 2;                 \
        const uint32_t db = da + TILE_E * 2;                                   \
        cp_async16(da + lc0 * 16,       ga + lc0 * 8);                         \
        cp_async16(da + (lc0 + 1) * 16, ga + (lc0 + 1) * 8);                   \
        cp_async16(db + lc0 * 16,       gb + lc0 * 8);                         \
        cp_async16(db + (lc0 + 1) * 16, gb + (lc0 + 1) * 8);                   \
        CP_COMMIT();                                                           \
    };                                                                         \
    issue(0);                                                                  \
    issue(1);                                                                  \
    for (int c = 0; c < (NC); c++) {                                           \
        if (c + 1 < (NC)) { CP_WAIT_1(); } else { CP_WAIT_0(); }               \
        __syncthreads();                                                       \
        if (c + 2 < (NC)) issue(c + 2);                                        \
        const uint32_t bA = s0 + (uint32_t)((c % 3) * BUF_E) * 2;              \
        const uint32_t bB = bA + TILE_E * 2;                                   \
        _Pragma("unroll")                                                      \
        for (int k16 = 0; k16 < 32; k16 += 16) {                               \
            uint32_t af[4][4], bf[2][4];                                       \
            _Pragma("unroll")                                                  \
            for (int mi = 0; mi < 4; mi++)                                     \
                LDSM4(af[mi], bA + (uint32_t)(((wm + mi * 16 + a_row) * SMS)   \
                                              + k16 + a_k) * 2);               \
            _Pragma("unroll")                                                  \
            for (int ni = 0; ni < 2; ni++)                                     \
                LDSM4(bf[ni], bB + (uint32_t)(((wn + ni * 16 + b_row) * SMS)   \
                                              + k16 + b_k) * 2);               \
            _Pragma("unroll")                                                  \
            for (int mi = 0; mi < 4; mi++)                                     \
                _Pragma("unroll")                                              \
                for (int nj = 0; nj < 4; nj++)                                 \
                    MMA_F16(acc[mi][nj], af[mi],                               \
                            bf[nj >> 1][(nj & 1) * 2],                         \
                            bf[nj >> 1][(nj & 1) * 2 + 1]);                    \
        }                                                                      \
    }

// ---------------------------------------------------------------------------
// Fused QKV projection: grid (16, 32, 3); z=0:Q(rope+scale), 1:K(rope),
// 2:V(transpose). Epilogue stages acc in smem f32, emits fp16 directly.
// ---------------------------------------------------------------------------
__global__ __launch_bounds__(256, 2) void mma_qkv(
    const __half* __restrict__ Xf,
    const __half* __restrict__ Wq, const __half* __restrict__ Wk,
    const __half* __restrict__ Wv,
    __half* __restrict__ Qf, __half* __restrict__ Kf, __half* __restrict__ Vt)
{
    extern __shared__ __half sm[];
    const uint32_t s0 = smem_u32(sm);
    const int tid = threadIdx.x;
    const int wid = tid >> 5, lane = tid & 31;
    const int zp = blockIdx.z;

    const __half* A = Xf + (long long)blockIdx.y * 128 * HIDDEN;
    const __half* W = (zp == 0) ? Wq : (zp == 1) ? Wk : Wv;
    const __half* B = W + (long long)blockIdx.x * 128 * HIDDEN;

    GEMM_MAINLOOP(A, B, HIDDEN >> 5)

    __syncthreads();   // all warps done reading smem buffers before staging

    // ---- stage accumulators to smem (f32, stride 133) ----
    float* fsm = reinterpret_cast<float*>(sm);
    const int gr = lane >> 2, tcc = (lane & 3) * 2;
    #pragma unroll
    for (int mi = 0; mi < 4; mi++) {
        const int r0 = wm + mi * 16 + gr;
        #pragma unroll
        for (int nj = 0; nj < 4; nj++) {
            const int col = wn + nj * 8 + tcc;
            fsm[r0 * STAGE_STRIDE + col]           = acc[mi][nj][0];
            fsm[r0 * STAGE_STRIDE + col + 1]       = acc[mi][nj][1];
            fsm[(r0 + 8) * STAGE_STRIDE + col]     = acc[mi][nj][2];
            fsm[(r0 + 8) * STAGE_STRIDE + col + 1] = acc[mi][nj][3];
        }
    }
    __syncthreads();

    if (zp < 2) {
        // ---- RoPE epilogue (Q: scaled, K: unscaled) ----
        const int r  = tid >> 1;
        const int j0 = (tid & 1) * 32;
        const long long gy = (long long)blockIdx.y * 128 + r;
        const int s = (int)(gy & (SEQ - 1));
        const float qsc = (zp == 0) ? 0.08838834764831845f : 1.0f;
        __half* dst = ((zp == 0) ? Qf : Kf) + gy * HIDDEN + blockIdx.x * 128;
        #pragma unroll 4
        for (int j = j0; j < j0 + 32; j += 2) {
            float v0a = fsm[r * STAGE_STRIDE + j];
            float v1a = fsm[r * STAGE_STRIDE + j + 64];
            float v0b = fsm[r * STAGE_STRIDE + j + 1];
            float v1b = fsm[r * STAGE_STRIDE + j + 65];
            float anga = (float)s * exp2f((float)j       * -0.20762050593046f);
            float angb = (float)s * exp2f((float)(j + 1) * -0.20762050593046f);
            float ca, sa, cb, sb2;
            sincosf(anga, &sa, &ca);
            sincosf(angb, &sb2, &cb);
            float o0a = (v0a * ca - v1a * sa) * qsc;
            float o1a = (v1a * ca + v0a * sa) * qsc;
            float o0b = (v0b * cb - v1b * sb2) * qsc;
            float o1b = (v1b * cb + v0b * sb2) * qsc;
            *(__half2*)(dst + j)      = __float22half2_rn(make_float2(o0a, o0b));
            *(__half2*)(dst + j + 64) = __float22half2_rn(make_float2(o1a, o1b));
        }
    } else {
        // ---- V transpose epilogue: Vt[((b*16+h)*128+d)*SEQ + s] ----
        const int d   = tid >> 1;
        const int si0 = (tid & 1) * 64;
        const int b   = (blockIdx.y * 128) >> 11;
        const int sbase = (blockIdx.y * 128) & (SEQ - 1);
        __half* dst = Vt + ((long long)((b * NH + blockIdx.x) * HD + d)) * SEQ
                         + sbase + si0;
        #pragma unroll 8
        for (int sl = 0; sl < 64; sl += 2) {
            float v0 = fsm[(si0 + sl) * STAGE_STRIDE + d];
            float v1 = fsm[(si0 + sl + 1) * STAGE_STRIDE + d];
            *(__half2*)(dst + sl) = __float22half2_rn(make_float2(v0, v1));
        }
    }
}

// ---------------------------------------------------------------------------
// Output projection: out[M,N] = Cf[M,K] @ Wo[N,K]^T  (f32 output)
// ---------------------------------------------------------------------------
__global__ __launch_bounds__(256, 2) void mma_out(
    const __half* __restrict__ Cf, const __half* __restrict__ Wo,
    float* __restrict__ C)
{
    extern __shared__ __half sm[];
    const uint32_t s0 = smem_u32(sm);
    const int tid = threadIdx.x;
    const int wid = tid >> 5, lane = tid & 31;

    const __half* A = Cf + (long long)blockIdx.y * 128 * HIDDEN;
    const __half* B = Wo + (long long)blockIdx.x * 128 * HIDDEN;
    C += (long long)blockIdx.y * 128 * HIDDEN + (long long)blockIdx.x * 128;

    GEMM_MAINLOOP(A, B, HIDDEN >> 5)

    const int gr = lane >> 2, tcc = (lane & 3) * 2;
    #pragma unroll
    for (int mi = 0; mi < 4; mi++) {
        const int row0 = wm + mi * 16 + gr;
        #pragma unroll
        for (int nj = 0; nj < 4; nj++) {
            const int col = wn + nj * 8 + tcc;
            *(float2*)(C + (long long)row0 * HIDDEN + col) =
                make_float2(acc[mi][nj][0], acc[mi][nj][1]);
            *(float2*)(C + (long long)(row0 + 8) * HIDDEN + col) =
                make_float2(acc[mi][nj][2], acc[mi][nj][3]);
        }
    }
}

// ---------------------------------------------------------------------------
// Fused flash attention (fp16), double-buffered 64-key KV tiles, 2 CTAs/SM.
// ---------------------------------------------------------------------------
#define FSTR 136
#define VSTR 72
#define QTILE_B (128*FSTR*2)
#define KTILE_B (64*FSTR*2)
#define VTILE_B (128*VSTR*2)
#define OFF_Q 0
#define OFF_K QTILE_B
#define OFF_V (OFF_K + 2*KTILE_B)
#define FLASH_SMEM (OFF_V + 2*VTILE_B)   /* 106496 */

__global__ __launch_bounds__(256, 2) void flash_attn(
    const __half* __restrict__ Qf_, const __half* __restrict__ Kf_,
    const __half* __restrict__ Vt_, __half* __restrict__ Cf)
{
    extern __shared__ __half sm[];
    const uint32_t s0 = smem_u32(sm);

    const int tid = threadIdx.x, wid = tid >> 5, lane = tid & 31;
    const int z = blockIdx.y, b = z >> 4, h = z & 15;
    const int q0 = blockIdx.x * 128;
    const long long SH = (long long)SEQ * HIDDEN;

    const __half* qf  = Qf_ + (long long)b * SH + h * HD + (long long)q0 * HIDDEN;
    const __half* kf0 = Kf_ + (long long)b * SH + h * HD;
    const __half* vt0 = Vt_ + (long long)z * HD * SEQ;

    {
        const int lrow = tid >> 1, lc0 = (tid & 1) * 8;
        const __half* g = qf + (long long)lrow * HIDDEN + lc0 * 8;
        const uint32_t d = s0 + OFF_Q + (uint32_t)(lrow * 272 + lc0 * 16);
        #pragma unroll
        for (int i = 0; i < 8; i++) cp_async16(d + i * 16, g + i * 8);
    }

    auto issueKV = [&](int kt) {
        const int st = kt & 1;
        const int kb = kt << 6;
        {
            const int lrow = tid >> 2;
            const int lc   = (tid & 3) * 4;
            const __half* g = kf0 + (long long)(kb + lrow) * HIDDEN + lc * 8;
            const uint32_t d = s0 + OFF_K + (uint32_t)(st * KTILE_B
                               + lrow * 272 + lc * 16);
            #pragma unroll
            for (int i = 0; i < 4; i++) cp_async16(d + i * 16, g + i * 8);
        }
        {
            const int lrow = tid >> 1;
            const int lc   = (tid & 1) * 4;
            const __half* g = vt0 + (long long)lrow * SEQ + kb + lc * 8;
            const uint32_t d = s0 + OFF_V + (uint32_t)(st * VTILE_B
                               + lrow * 144 + lc * 16);
            #pragma unroll
            for (int i = 0; i < 4; i++) cp_async16(d + i * 16, g + i * 8);
        }
        CP_COMMIT();
    };

    issueKV(0);

    const int i8 = lane & 7, msel = lane >> 3;
    const int a_row = i8 + ((msel & 1) << 3);
    const int a_k   = (msel >> 1) << 3;
    const int b_row = i8 + ((msel >> 1) << 3);
    const int b_k   = (msel & 1) << 3;
    const int wm = wid << 4;

    float o[16][4];
    #pragma unroll
    for (int t = 0; t < 16; t++)
        #pragma unroll
        for (int r = 0; r < 4; r++) o[t][r] = 0.0f;
    float m0 = -1e30f, m1 = -1e30f, l0 = 0.0f, l1 = 0.0f;

    const uint32_t bQ = s0 + OFF_Q;

    for (int kt = 0; kt < 32; kt++) {
        if (kt + 1 < 32) { issueKV(kt + 1); CP_WAIT_1(); }
        else             { CP_WAIT_0(); }
        __syncthreads();

        const uint32_t bK = s0 + OFF_K + (uint32_t)((kt & 1) * KTILE_B);
        const uint32_t bV = s0 + OFF_V + (uint32_t)((kt & 1) * VTILE_B);

        float c[8][4];
        #pragma unroll
        for (int t = 0; t < 8; t++)
            #pragma unroll
            for (int r = 0; r < 4; r++) c[t][r] = 0.0f;

        #pragma unroll
        for (int k16 = 0; k16 < 128; k16 += 16) {
            uint32_t af[4];
            LDSM4(af, bQ + (uint32_t)(((wm + a_row) * FSTR) + k16 + a_k) * 2);
            #pragma unroll
            for (int g = 0; g < 4; g++) {
                uint32_t bfr[4];
                LDSM4(bfr, bK + (uint32_t)((((g << 4) + b_row) * FSTR) + k16 + b_k) * 2);
                MMA_F16(c[(g << 1) + 0], af, bfr[0], bfr[1]);
                MMA_F16(c[(g << 1) + 1], af, bfr[2], bfr[3]);
            }
        }

        float mx0 = c[0][0], mx1 = c[0][2];
        #pragma unroll
        for (int t = 0; t < 8; t++) {
            mx0 = fmaxf(mx0, fmaxf(c[t][0], c[t][1]));
            mx1 = fmaxf(mx1, fmaxf(c[t][2], c[t][3]));
        }
        mx0 = fmaxf(mx0, __shfl_xor_sync(0xFFFFFFFFu, mx0, 1));
        mx0 = fmaxf(mx0, __shfl_xor_sync(0xFFFFFFFFu, mx0, 2));
        mx1 = fmaxf(mx1, __shfl_xor_sync(0xFFFFFFFFu, mx1, 1));
        mx1 = fmaxf(mx1, __shfl_xor_sync(0xFFFFFFFFu, mx1, 2));
        const float nm0 = fmaxf(m0, mx0), nm1 = fmaxf(m1, mx1);
        const float al0 = __expf(m0 - nm0), al1 = __expf(m1 - nm1);
        m0 = nm0; m1 = nm1;

        float s0s = 0.0f, s1s = 0.0f;
        #pragma unroll
        for (int t = 0; t < 8; t++) {
            c[t][0] = __expf(c[t][0] - m0);
            c[t][1] = __expf(c[t][1] - m0);
            c[t][2] = __expf(c[t][2] - m1);
            c[t][3] = __expf(c[t][3] - m1);
            s0s += c[t][0] + c[t][1];
            s1s += c[t][2] + c[t][3];
        }
        s0s += __shfl_xor_sync(0xFFFFFFFFu, s0s, 1);
        s0s += __shfl_xor_sync(0xFFFFFFFFu, s0s, 2);
        s1s += __shfl_xor_sync(0xFFFFFFFFu, s1s, 1);
        s1s += __shfl_xor_sync(0xFFFFFFFFu, s1s, 2);
        l0 = l0 * al0 + s0s;
        l1 = l1 * al1 + s1s;

        #pragma unroll
        for (int t = 0; t < 16; t++) {
            o[t][0] *= al0; o[t][1] *= al0;
            o[t][2] *= al1; o[t][3] *= al1;
        }

        #pragma unroll
        for (int j = 0; j < 4; j++) {
            uint32_t ph[4];
            ph[0] = pack_h2(c[2*j][0],   c[2*j][1]);
            ph[1] = pack_h2(c[2*j][2],   c[2*j][3]);
            ph[2] = pack_h2(c[2*j+1][0], c[2*j+1][1]);
            ph[3] = pack_h2(c[2*j+1][2], c[2*j+1][3]);
            #pragma unroll
            for (int g = 0; g < 8; g++) {
                uint32_t vf[4];
                LDSM4(vf, bV + (uint32_t)((((g << 4) + b_row) * VSTR) + (j << 4) + b_k) * 2);
                MMA_F16(o[(g << 1) + 0], ph, vf[0], vf[1]);
                MMA_F16(o[(g << 1) + 1], ph, vf[2], vf[3]);
            }
        }
        __syncthreads();
    }

    // ---- epilogue: O /= l, write fp16 ctx ----
    const float i0 = 1.0f / l0, i1 = 1.0f / l1;
    const int r0 = q0 + wm + (lane >> 2);
    const int tc = (lane & 3) * 2;
    __half* c0p = Cf + (long long)(b * SEQ + r0) * HIDDEN + h * HD;
    __half* c1p = c0p + 8 * HIDDEN;
    #pragma unroll
    for (int t = 0; t < 16; t++) {
        const int col = t * 8 + tc;
        *(__half2*)(c0p + col) = __float22half2_rn(make_float2(o[t][0] * i0, o[t][1] * i0));
        *(__half2*)(c1p + col) = __float22half2_rn(make_float2(o[t][2] * i1, o[t][3] * i1));
    }
}

// ---------------------------------------------------------------------------
// Merged fp32 -> fp16 convert: region 0 = X (8192 blocks), 1..4 = weights
// (4096 blocks each). One launch instead of five.
// ---------------------------------------------------------------------------
#define XN4   (ROWS * HIDDEN / 4)      /* 2097152 -> 8192 blocks */
#define WN4   (HIDDEN * HIDDEN / 4)    /* 1048576 -> 4096 blocks */
#define XBLK  (XN4 / 256)
#define WBLK  (WN4 / 256)

__global__ __launch_bounds__(256) void cvt_all(
    const float* __restrict__ X,
    const float* __restrict__ Wq, const float* __restrict__ Wk,
    const float* __restrict__ Wv, const float* __restrict__ Wo,
    __half* __restrict__ Xf,
    __half* __restrict__ Wqf, __half* __restrict__ Wkf,
    __half* __restrict__ Wvf, __half* __restrict__ Wof)
{
    int blk = blockIdx.x;
    const float* src;
    __half* dst;
    int i;
    if (blk < XBLK) {
        src = X;  dst = Xf;  i = blk * 256 + threadIdx.x;
    } else {
        int r = (blk - XBLK) / WBLK;       // 0..3
        int rb = (blk - XBLK) - r * WBLK;
        src = (r == 0) ? Wq : (r == 1) ? Wk : (r == 2) ? Wv : Wo;
        dst = (r == 0) ? Wqf : (r == 1) ? Wkf : (r == 2) ? Wvf : Wof;
        i = rb * 256 + threadIdx.x;
    }
    float4 x = *(const float4*)(src + (long long)i * 4);
    *(__half2*)(dst + (long long)i * 4)     = __float22half2_rn(make_float2(x.x, x.y));
    *(__half2*)(dst + (long long)i * 4 + 2) = __float22half2_rn(make_float2(x.z, x.w));
}

// ---------------------------------------------------------------------------
extern "C" void kernel_launch(void* const* d_in, const int* in_sizes, int n_in,
                              void* d_out, int out_size)
{
    const float* X  = (const float*)d_in[0];
    const float* Wq = (const float*)d_in[1];
    const float* Wk = (const float*)d_in[2];
    const float* Wv = (const float*)d_in[3];
    const float* Wo = (const float*)d_in[4];
    float* out = (float*)d_out;

    __half *Xf, *Wqf, *Wkf, *Wvf, *Wof, *Qf, *Kf, *Vt, *Cf;
    cudaGetSymbolAddress((void**)&Xf,  g_Xf);
    cudaGetSymbolAddress((void**)&Wqf, g_Wqf);
    cudaGetSymbolAddress((void**)&Wkf, g_Wkf);
    cudaGetSymbolAddress((void**)&Wvf, g_Wvf);
    cudaGetSymbolAddress((void**)&Wof, g_Wof);
    cudaGetSymbolAddress((void**)&Qf,  g_Qf);
    cudaGetSymbolAddress((void**)&Kf,  g_Kf);
    cudaGetSymbolAddress((void**)&Vt,  g_Vt);
    cudaGetSymbolAddress((void**)&Cf,  g_Cf);

    cudaFuncSetAttribute(mma_qkv, cudaFuncAttributeMaxDynamicSharedMemorySize,
                         QKV_SMEM);
    cudaFuncSetAttribute(mma_out, cudaFuncAttributeMaxDynamicSharedMemorySize,
                         GEMM_SMEM);
    cudaFuncSetAttribute(flash_attn, cudaFuncAttributeMaxDynamicSharedMemorySize,
                         FLASH_SMEM);

    dim3 blk(256);

    // Convert all inputs to fp16 in one launch
    cvt_all<<<XBLK + 4 * WBLK, blk>>>(X, Wq, Wk, Wv, Wo,
                                      Xf, Wqf, Wkf, Wvf, Wof);

    // Fused QKV projections + rope/scale/transpose epilogues -> fp16
    mma_qkv<<<dim3(HIDDEN / 128, ROWS / 128, 3), blk, QKV_SMEM>>>(
        Xf, Wqf, Wkf, Wvf, Qf, Kf, Vt);

    // Fused attention -> fp16 ctx
    flash_attn<<<dim3(SEQ / 128, BATCH * NH), blk, FLASH_SMEM>>>(Qf, Kf, Vt, Cf);

    // Output projection -> f32 out
    mma_out<<<dim3(HIDDEN / 128, ROWS / 128), blk, GEMM_SMEM>>>(Cf, Wof, out);
}